// round 7
// baseline (speedup 1.0000x reference)
#include <cuda_runtime.h>
#include <cuda_fp16.h>
#include <cstdint>

// x:(8,128,128,64) Woff:(3,3,64,18) boff:(18) W:(3,3,576,128)->(5184,128) b:(128)
// out:(8,128,128,128) f32

#define CHUNKS 81  // 5184/64; chunk q=(tap=q/9, ts=q%9), 64 channels

__device__ float g_off[8 * 128 * 128 * 18];
__device__ __half g_xh[8 * 128 * 128 * 64];         // x in fp16 (16.8MB)
__device__ __half g_samp[8 * 128 * 128 * 9 * 64];   // (pixel, ts, c) 151MB
__device__ __half g_wt[CHUNKS * 128 * 64];          // [q][n][c] K-major

__device__ __forceinline__ uint32_t smem_u32(const void* p) {
  uint32_t a;
  asm("{ .reg .u64 t; cvta.to.shared.u64 t, %1; cvt.u32.u64 %0, t; }"
      : "=r"(a) : "l"(p));
  return a;
}

#define SWZ(o) ((o) ^ (((o) >> 3) & 0x70))
#define FMA2(d, a, bb) \
  asm("fma.rn.f32x2 %0, %1, %2, %0;" : "+l"(d) : "l"(a), "l"(bb))

// ------------------------------------------------------------------
// K0: x -> fp16
// ------------------------------------------------------------------
__global__ __launch_bounds__(256) void xh_kernel(const float* __restrict__ x) {
  int i = blockIdx.x * 256 + threadIdx.x;
  float2 v = *(const float2*)&x[2 * i];
  *(__half2*)&g_xh[2 * i] = __floats2half2_rn(v.x, v.y);
}

// ------------------------------------------------------------------
// K1: offsets conv3x3 + boff. FFMA2 packed accumulators (9 o-pairs).
// ------------------------------------------------------------------
__global__ __launch_bounds__(128) void offsets_kernel(
    const float* __restrict__ x, const float* __restrict__ Woff,
    const float* __restrict__ boff) {
  __shared__ float xs[3][128][20];
  __shared__ float wofs[9][16][18];
  const int bh = blockIdx.x;
  const int b = bh >> 7, h = bh & 127;
  const int w = threadIdx.x;

  unsigned long long acc2[9];
#pragma unroll
  for (int o = 0; o < 9; o++) acc2[o] = 0ull;

#pragma unroll 1
  for (int cc = 0; cc < 64; cc += 16) {
    for (int fid = threadIdx.x; fid < 1536; fid += 128) {
      int r = fid / 512;
      int rem = fid - r * 512;
      int ww = rem >> 2;
      int cq = (rem & 3) * 4;
      int y = h + r - 1;
      float4 v = make_float4(0.f, 0.f, 0.f, 0.f);
      if ((unsigned)y < 128u)
        v = *(const float4*)&x[(((b * 128 + y) * 128 + ww) * 64) + cc + cq];
      *(float4*)&xs[r][ww][cq] = v;
    }
    for (int idx = threadIdx.x; idx < 9 * 16 * 18; idx += 128) {
      int rs = idx / 288;
      ((float*)wofs)[idx] = Woff[idx + rs * 864 + cc * 18];
    }
    __syncthreads();

#pragma unroll 1
    for (int rs = 0; rs < 9; rs++) {
      int r = rs / 3;
      int s = rs - r * 3;
      int wp = w + s - 1;
      if ((unsigned)wp < 128u) {
        float4 q0 = *(const float4*)&xs[r][wp][0];
        float4 q1 = *(const float4*)&xs[r][wp][4];
        float4 q2 = *(const float4*)&xs[r][wp][8];
        float4 q3 = *(const float4*)&xs[r][wp][12];
        float xv[16] = {q0.x, q0.y, q0.z, q0.w, q1.x, q1.y, q1.z, q1.w,
                        q2.x, q2.y, q2.z, q2.w, q3.x, q3.y, q3.z, q3.w};
#pragma unroll
        for (int c = 0; c < 16; c++) {
          unsigned long long ad;
          asm("mov.b64 %0, {%1, %1};" : "=l"(ad) : "f"(xv[c]));
#pragma unroll
          for (int op = 0; op < 9; op++) {
            unsigned long long bp =
                *(const unsigned long long*)&wofs[rs][c][2 * op];
            FMA2(acc2[op], ad, bp);
          }
        }
      }
    }
    __syncthreads();
  }

  int base = (bh * 128 + w) * 18;
#pragma unroll
  for (int op = 0; op < 9; op++) {
    float lo, hi;
    asm("mov.b64 {%0, %1}, %2;" : "=f"(lo), "=f"(hi) : "l"(acc2[op]));
    g_off[base + 2 * op] = lo + boff[2 * op];
    g_off[base + 2 * op + 1] = hi + boff[2 * op + 1];
  }
}

// ------------------------------------------------------------------
// K2: bilinear sample (fp16 x) -> fp16. One warp per (pixel, ts).
// ------------------------------------------------------------------
__global__ __launch_bounds__(256) void sample_kernel() {
  const int bh = blockIdx.x;
  const int b = bh >> 7, h = bh & 127;
  const int warp = threadIdx.x >> 5, lane = threadIdx.x & 31;
  const __half* xb = g_xh + ((size_t)b << 20);

  for (int t = warp; t < 128 * 9; t += 8) {
    int p = t / 9;
    int ts = t - p * 9;
    int pix = bh * 128 + p;
    float ox = g_off[pix * 18 + 2 * ts];
    float oy = g_off[pix * 18 + 2 * ts + 1];
    float lx = (float)(p + (ts % 3) - 1) + ox;
    float ly = (float)(h + (ts / 3) - 1) + oy;
    lx = fminf(fmaxf(lx, 0.f), 127.f);
    ly = fminf(fmaxf(ly, 0.f), 127.f);
    float x0f = floorf(lx), y0f = floorf(ly);
    int xi0 = (int)x0f, yi0 = (int)y0f;
    int xi1 = min(xi0 + 1, 127), yi1 = min(yi0 + 1, 127);
    float dx0 = lx - x0f, dy0 = ly - y0f;
    float dx1 = (float)xi1 - lx, dy1 = (float)yi1 - ly;
    float wa = dx1 * dy1, wb = dx1 * dy0, wc = dx0 * dy1, wd = dx0 * dy0;

    int r0 = yi0 << 13, r1 = yi1 << 13;
    int cx0 = xi0 << 6, cx1 = xi1 << 6;
    int cl = 2 * lane;
    float2 Ia = __half22float2(*(const __half2*)&xb[r0 + cx0 + cl]);
    float2 Ib = __half22float2(*(const __half2*)&xb[r1 + cx0 + cl]);
    float2 Ic = __half22float2(*(const __half2*)&xb[r0 + cx1 + cl]);
    float2 Id = __half22float2(*(const __half2*)&xb[r1 + cx1 + cl]);
    float vx = wa * Ia.x + wb * Ib.x + wc * Ic.x + wd * Id.x;
    float vy = wa * Ia.y + wb * Ib.y + wc * Ic.y + wd * Id.y;
    *(__half2*)&g_samp[((size_t)pix * 9 + ts) * 64 + cl] =
        __floats2half2_rn(vx, vy);
  }
}

// ------------------------------------------------------------------
// K3: W (5184,128) -> fp16 [q][n][c]
// ------------------------------------------------------------------
__global__ __launch_bounds__(256) void wprep_kernel(const float* __restrict__ Wm) {
  int i = blockIdx.x * 256 + threadIdx.x;
  int c = i & 63;
  int n = (i >> 6) & 127;
  int q = i >> 13;
  g_wt[i] = __float2half(Wm[(q * 64 + c) * 128 + n]);
}

// ------------------------------------------------------------------
// K4: fp16 mma.sync implicit GEMM. One block per (b,h) row.
// M=128,N=128,K=5184. 4 warps, warp tile m64 x n64. 3-stage cp.async.
// Stage = A(16KB)+B(16KB) = 32KB; 3 stages = 96KB; 2 CTA/SM.
// ------------------------------------------------------------------
__global__ __launch_bounds__(128, 2) void gemm_kernel(
    const float* __restrict__ bias, float* __restrict__ out) {
  extern __shared__ __align__(16) char smraw[];
  const uint32_t sb = smem_u32(smraw);
  const uint32_t tiles = (sb + 1023u) & ~1023u;

  const int tid = threadIdx.x, lane = tid & 31, wid = tid >> 5;
  const int bh = blockIdx.x;
  const int b = bh >> 7, h = bh & 127;

  auto load_chunk = [&](int q, int st) {
    int tap = q / 9, ts = q - tap * 9;
    int r = tap / 3, s = tap - r * 3;
    int y = h + r - 1;
    uint32_t abase = tiles + (uint32_t)st * 32768u;
    uint32_t bbase = abase + 16384u;
#pragma unroll
    for (int j = 0; j < 8; j++) {
      int seg = j * 128 + tid;
      int arow = seg >> 3, acol = seg & 7;
      int wp = arow + s - 1;
      bool ok = ((unsigned)y < 128u) && ((unsigned)wp < 128u);
      const __half* src =
          ok ? g_samp + ((((size_t)((b * 128 + y) * 128 + wp)) * 9 + ts) * 64 +
                         acol * 8)
             : g_samp;
      uint32_t dst = abase + SWZ(arow * 128 + acol * 16);
      int sz = ok ? 16 : 0;
      asm volatile("cp.async.ca.shared.global [%0], [%1], 16, %2;" ::"r"(dst),
                   "l"(src), "r"(sz));
    }
#pragma unroll
    for (int j = 0; j < 8; j++) {
      int seg = j * 128 + tid;
      int brow = seg >> 3, bcol = seg & 7;
      const __half* src = g_wt + ((size_t)q * 8192 + brow * 64 + bcol * 8);
      uint32_t dst = bbase + SWZ(brow * 128 + bcol * 16);
      asm volatile("cp.async.ca.shared.global [%0], [%1], 16;" ::"r"(dst),
                   "l"(src));
    }
    asm volatile("cp.async.commit_group;" ::);
  };

  const int m0 = (wid & 1) * 64;
  const int n0 = (wid >> 1) * 64;

  float acc[4][8][4];
#pragma unroll
  for (int nt = 0; nt < 8; nt++) {
    int n = n0 + nt * 8 + 2 * (lane & 3);
    float b0 = bias[n], b1 = bias[n + 1];
#pragma unroll
    for (int mt = 0; mt < 4; mt++) {
      acc[mt][nt][0] = b0;
      acc[mt][nt][1] = b1;
      acc[mt][nt][2] = b0;
      acc[mt][nt][3] = b1;
    }
  }

  load_chunk(0, 0);
  load_chunk(1, 1);

  for (int c = 0; c < CHUNKS; c++) {
    const int st = c % 3;
    if (c + 1 < CHUNKS)
      asm volatile("cp.async.wait_group 1;" ::);
    else
      asm volatile("cp.async.wait_group 0;" ::);
    __syncthreads();
    if (c + 2 < CHUNKS) load_chunk(c + 2, (c + 2) % 3);

    const uint32_t abase = tiles + (uint32_t)st * 32768u;
    const uint32_t bbase = abase + 16384u;
#pragma unroll
    for (int ks = 0; ks < 4; ks++) {
      uint32_t ar[4][4], br[8][2];
#pragma unroll
      for (int mt = 0; mt < 4; mt++) {
        int row = m0 + mt * 16 + (lane & 15);
        uint32_t addr = abase + SWZ(row * 128 + ks * 32 + ((lane >> 4) << 4));
        asm volatile(
            "ldmatrix.sync.aligned.m8n8.x4.shared.b16 {%0,%1,%2,%3}, [%4];"
            : "=r"(ar[mt][0]), "=r"(ar[mt][1]), "=r"(ar[mt][2]),
              "=r"(ar[mt][3])
            : "r"(addr));
      }
#pragma unroll
      for (int np = 0; np < 4; np++) {
        int rowb = n0 + np * 16 + ((lane >> 4) << 3) + (lane & 7);
        uint32_t addr =
            bbase + SWZ(rowb * 128 + ks * 32 + (((lane >> 3) & 1) << 4));
        asm volatile(
            "ldmatrix.sync.aligned.m8n8.x4.shared.b16 {%0,%1,%2,%3}, [%4];"
            : "=r"(br[2 * np][0]), "=r"(br[2 * np][1]),
              "=r"(br[2 * np + 1][0]), "=r"(br[2 * np + 1][1])
            : "r"(addr));
      }
#pragma unroll
      for (int mt = 0; mt < 4; mt++)
#pragma unroll
        for (int nt = 0; nt < 8; nt++) {
          asm volatile(
              "mma.sync.aligned.m16n8k16.row.col.f32.f16.f16.f32 "
              "{%0,%1,%2,%3}, {%4,%5,%6,%7}, {%8,%9}, {%0,%1,%2,%3};"
              : "+f"(acc[mt][nt][0]), "+f"(acc[mt][nt][1]),
                "+f"(acc[mt][nt][2]), "+f"(acc[mt][nt][3])
              : "r"(ar[mt][0]), "r"(ar[mt][1]), "r"(ar[mt][2]),
                "r"(ar[mt][3]), "r"(br[nt][0]), "r"(br[nt][1]));
        }
    }
  }

  // epilogue
  float* ob = out + (size_t)bh * 16384;
#pragma unroll
  for (int mt = 0; mt < 4; mt++) {
    int row0 = m0 + mt * 16 + (lane >> 2);
#pragma unroll
    for (int nt = 0; nt < 8; nt++) {
      int n = n0 + nt * 8 + 2 * (lane & 3);
      *(float2*)&ob[row0 * 128 + n] =
          make_float2(acc[mt][nt][0], acc[mt][nt][1]);
      *(float2*)&ob[(row0 + 8) * 128 + n] =
          make_float2(acc[mt][nt][2], acc[mt][nt][3]);
    }
  }
}

extern "C" void kernel_launch(void* const* d_in, const int* in_sizes, int n_in,
                              void* d_out, int out_size) {
  (void)in_sizes;
  (void)n_in;
  (void)out_size;
  const float* x = (const float*)d_in[0];
  const float* Woff = (const float*)d_in[1];
  const float* boff = (const float*)d_in[2];
  const float* Wm = (const float*)d_in[3];
  const float* bias = (const float*)d_in[4];
  float* out = (float*)d_out;

  const int smem_bytes = 3 * 32768 + 1024;
  cudaFuncSetAttribute(gemm_kernel, cudaFuncAttributeMaxDynamicSharedMemorySize,
                       smem_bytes);

  xh_kernel<<<16384, 256>>>(x);
  offsets_kernel<<<1024, 128>>>(x, Woff, boff);
  sample_kernel<<<1024, 256>>>();
  wprep_kernel<<<2592, 256>>>(Wm);
  gemm_kernel<<<1024, 128, smem_bytes>>>(bias, out);
}

// round 8
// speedup vs baseline: 1.1494x; 1.1494x over previous
#include <cuda_runtime.h>
#include <cuda_fp16.h>
#include <cstdint>

// x:(8,128,128,64) Woff:(3,3,64,18) boff:(18) W:(3,3,576,128)->(5184,128) b:(128)
// out:(8,128,128,128) f32

#define CHUNKS 81  // 5184/64; chunk q=(tap=q/9, ts=q%9), 64 channels

__device__ float g_off[8 * 128 * 128 * 18];
__device__ __half g_xh[8 * 128 * 128 * 64];         // x in fp16 (16.8MB)
__device__ __half g_samp[8 * 128 * 128 * 9 * 64];   // (pixel, ts, c) 151MB
__device__ __half g_wt[CHUNKS * 128 * 64];          // [q][n][c] K-major

__device__ __forceinline__ uint32_t smem_u32(const void* p) {
  uint32_t a;
  asm("{ .reg .u64 t; cvta.to.shared.u64 t, %1; cvt.u32.u64 %0, t; }"
      : "=r"(a) : "l"(p));
  return a;
}

#define SWZ(o) ((o) ^ (((o) >> 3) & 0x70))
#define FMA2(d, a, bb) \
  asm("fma.rn.f32x2 %0, %1, %2, %0;" : "+l"(d) : "l"(a), "l"(bb))

// ------------------------------------------------------------------
// K1: offsets conv3x3 + boff (FFMA2), fused x->fp16 for row h.
// One block per (b,h) row, 128 threads.
// ------------------------------------------------------------------
__global__ __launch_bounds__(128) void offsets_kernel(
    const float* __restrict__ x, const float* __restrict__ Woff,
    const float* __restrict__ boff) {
  __shared__ float xs[3][128][20];
  __shared__ float wofs[9][16][18];
  const int bh = blockIdx.x;
  const int b = bh >> 7, h = bh & 127;
  const int w = threadIdx.x;

  unsigned long long acc2[9];
#pragma unroll
  for (int o = 0; o < 9; o++) acc2[o] = 0ull;

#pragma unroll 1
  for (int cc = 0; cc < 64; cc += 16) {
    for (int fid = threadIdx.x; fid < 1536; fid += 128) {
      int r = fid / 512;
      int rem = fid - r * 512;
      int ww = rem >> 2;
      int cq = (rem & 3) * 4;
      int y = h + r - 1;
      float4 v = make_float4(0.f, 0.f, 0.f, 0.f);
      if ((unsigned)y < 128u)
        v = *(const float4*)&x[(((b * 128 + y) * 128 + ww) * 64) + cc + cq];
      *(float4*)&xs[r][ww][cq] = v;
    }
    for (int idx = threadIdx.x; idx < 9 * 16 * 18; idx += 128) {
      int rs = idx / 288;
      ((float*)wofs)[idx] = Woff[idx + rs * 864 + cc * 18];
    }
    __syncthreads();

    // fused fp16 conversion of row h (xs[1] holds y=h)
    {
      __half2 hv[8];
#pragma unroll
      for (int c = 0; c < 8; c++)
        hv[c] = __floats2half2_rn(xs[1][w][2 * c], xs[1][w][2 * c + 1]);
      *(uint4*)&g_xh[((size_t)bh * 128 + w) * 64 + cc] = *(uint4*)&hv[0];
      *(uint4*)&g_xh[((size_t)bh * 128 + w) * 64 + cc + 8] = *(uint4*)&hv[4];
    }

#pragma unroll 1
    for (int rs = 0; rs < 9; rs++) {
      int r = rs / 3;
      int s = rs - r * 3;
      int wp = w + s - 1;
      if ((unsigned)wp < 128u) {
        float4 q0 = *(const float4*)&xs[r][wp][0];
        float4 q1 = *(const float4*)&xs[r][wp][4];
        float4 q2 = *(const float4*)&xs[r][wp][8];
        float4 q3 = *(const float4*)&xs[r][wp][12];
        float xv[16] = {q0.x, q0.y, q0.z, q0.w, q1.x, q1.y, q1.z, q1.w,
                        q2.x, q2.y, q2.z, q2.w, q3.x, q3.y, q3.z, q3.w};
#pragma unroll
        for (int c = 0; c < 16; c++) {
          unsigned long long ad;
          asm("mov.b64 %0, {%1, %1};" : "=l"(ad) : "f"(xv[c]));
#pragma unroll
          for (int op = 0; op < 9; op++) {
            unsigned long long bp =
                *(const unsigned long long*)&wofs[rs][c][2 * op];
            FMA2(acc2[op], ad, bp);
          }
        }
      }
    }
    __syncthreads();
  }

  int base = (bh * 128 + w) * 18;
#pragma unroll
  for (int op = 0; op < 9; op++) {
    float lo, hi;
    asm("mov.b64 {%0, %1}, %2;" : "=f"(lo), "=f"(hi) : "l"(acc2[op]));
    g_off[base + 2 * op] = lo + boff[2 * op];
    g_off[base + 2 * op + 1] = hi + boff[2 * op + 1];
  }
}

// ------------------------------------------------------------------
// K2: bilinear sample (fp16 x) -> fp16. One warp per (pixel, ts).
// ------------------------------------------------------------------
__global__ __launch_bounds__(256) void sample_kernel() {
  const int bh = blockIdx.x;
  const int b = bh >> 7, h = bh & 127;
  const int warp = threadIdx.x >> 5, lane = threadIdx.x & 31;
  const __half* xb = g_xh + ((size_t)b << 20);

#pragma unroll 2
  for (int t = warp; t < 128 * 9; t += 8) {
    int p = t / 9;
    int ts = t - p * 9;
    int pix = bh * 128 + p;
    float ox = g_off[pix * 18 + 2 * ts];
    float oy = g_off[pix * 18 + 2 * ts + 1];
    float lx = (float)(p + (ts % 3) - 1) + ox;
    float ly = (float)(h + (ts / 3) - 1) + oy;
    lx = fminf(fmaxf(lx, 0.f), 127.f);
    ly = fminf(fmaxf(ly, 0.f), 127.f);
    float x0f = floorf(lx), y0f = floorf(ly);
    int xi0 = (int)x0f, yi0 = (int)y0f;
    int xi1 = min(xi0 + 1, 127), yi1 = min(yi0 + 1, 127);
    float dx0 = lx - x0f, dy0 = ly - y0f;
    float dx1 = (float)xi1 - lx, dy1 = (float)yi1 - ly;
    float wa = dx1 * dy1, wb = dx1 * dy0, wc = dx0 * dy1, wd = dx0 * dy0;

    int r0 = yi0 << 13, r1 = yi1 << 13;
    int cx0 = xi0 << 6, cx1 = xi1 << 6;
    int cl = 2 * lane;
    float2 Ia = __half22float2(*(const __half2*)&xb[r0 + cx0 + cl]);
    float2 Ib = __half22float2(*(const __half2*)&xb[r1 + cx0 + cl]);
    float2 Ic = __half22float2(*(const __half2*)&xb[r0 + cx1 + cl]);
    float2 Id = __half22float2(*(const __half2*)&xb[r1 + cx1 + cl]);
    float vx = wa * Ia.x + wb * Ib.x + wc * Ic.x + wd * Id.x;
    float vy = wa * Ia.y + wb * Ib.y + wc * Ic.y + wd * Id.y;
    *(__half2*)&g_samp[((size_t)pix * 9 + ts) * 64 + cl] =
        __floats2half2_rn(vx, vy);
  }
}

// ------------------------------------------------------------------
// K3: W (5184,128) -> fp16 [q][n][c]
// ------------------------------------------------------------------
__global__ __launch_bounds__(256) void wprep_kernel(const float* __restrict__ Wm) {
  int i = blockIdx.x * 256 + threadIdx.x;
  int c = i & 63;
  int n = (i >> 6) & 127;
  int q = i >> 13;
  g_wt[i] = __float2half(Wm[(q * 64 + c) * 128 + n]);
}

// ------------------------------------------------------------------
// K4: fp16 mma.sync implicit GEMM. One block per (b,h) row.
// M=128,N=128,K=5184. 8 warps m64xn32. 3-stage cp.async, 1 sync/chunk.
// Stage = A(16KB)+B(16KB) = 32KB; 3 stages = 96KB; 2 CTA/SM, 16 warps/SM.
// ------------------------------------------------------------------
__global__ __launch_bounds__(256, 2) void gemm_kernel(
    const float* __restrict__ bias, float* __restrict__ out) {
  extern __shared__ __align__(16) char smraw[];
  const uint32_t sb = smem_u32(smraw);
  const uint32_t tiles = (sb + 1023u) & ~1023u;

  const int tid = threadIdx.x, lane = tid & 31, wid = tid >> 5;
  const int bh = blockIdx.x;
  const int b = bh >> 7, h = bh & 127;

  auto load_chunk = [&](int q, int st) {
    int tap = q / 9, ts = q - tap * 9;
    int r = tap / 3, s = tap - r * 3;
    int y = h + r - 1;
    uint32_t abase = tiles + (uint32_t)st * 32768u;
    uint32_t bbase = abase + 16384u;
#pragma unroll
    for (int j = 0; j < 4; j++) {
      int seg = j * 256 + tid;
      int arow = seg >> 3, acol = seg & 7;
      int wp = arow + s - 1;
      bool ok = ((unsigned)y < 128u) && ((unsigned)wp < 128u);
      const __half* src =
          ok ? g_samp + ((((size_t)((b * 128 + y) * 128 + wp)) * 9 + ts) * 64 +
                         acol * 8)
             : g_samp;
      uint32_t dst = abase + SWZ(arow * 128 + acol * 16);
      int sz = ok ? 16 : 0;
      asm volatile("cp.async.cg.shared.global [%0], [%1], 16, %2;" ::"r"(dst),
                   "l"(src), "r"(sz));
    }
#pragma unroll
    for (int j = 0; j < 4; j++) {
      int seg = j * 256 + tid;
      int brow = seg >> 3, bcol = seg & 7;
      const __half* src = g_wt + ((size_t)q * 8192 + brow * 64 + bcol * 8);
      uint32_t dst = bbase + SWZ(brow * 128 + bcol * 16);
      asm volatile("cp.async.cg.shared.global [%0], [%1], 16;" ::"r"(dst),
                   "l"(src));
    }
    asm volatile("cp.async.commit_group;" ::);
  };

  const int m0 = (wid & 1) * 64;
  const int n0 = (wid >> 1) * 32;

  float acc[4][4][4];
#pragma unroll
  for (int nt = 0; nt < 4; nt++) {
    int n = n0 + nt * 8 + 2 * (lane & 3);
    float b0 = bias[n], b1 = bias[n + 1];
#pragma unroll
    for (int mt = 0; mt < 4; mt++) {
      acc[mt][nt][0] = b0;
      acc[mt][nt][1] = b1;
      acc[mt][nt][2] = b0;
      acc[mt][nt][3] = b1;
    }
  }

  load_chunk(0, 0);
  load_chunk(1, 1);

  for (int c = 0; c < CHUNKS; c++) {
    const int st = c % 3;
    if (c + 1 < CHUNKS)
      asm volatile("cp.async.wait_group 1;" ::);
    else
      asm volatile("cp.async.wait_group 0;" ::);
    __syncthreads();
    if (c + 2 < CHUNKS) load_chunk(c + 2, (c + 2) % 3);

    const uint32_t abase = tiles + (uint32_t)st * 32768u;
    const uint32_t bbase = abase + 16384u;
#pragma unroll
    for (int ks = 0; ks < 4; ks++) {
      uint32_t ar[4][4], br[4][2];
#pragma unroll
      for (int mt = 0; mt < 4; mt++) {
        int row = m0 + mt * 16 + (lane & 15);
        uint32_t addr = abase + SWZ(row * 128 + ks * 32 + ((lane >> 4) << 4));
        asm volatile(
            "ldmatrix.sync.aligned.m8n8.x4.shared.b16 {%0,%1,%2,%3}, [%4];"
            : "=r"(ar[mt][0]), "=r"(ar[mt][1]), "=r"(ar[mt][2]),
              "=r"(ar[mt][3])
            : "r"(addr));
      }
#pragma unroll
      for (int np = 0; np < 2; np++) {
        int rowb = n0 + np * 16 + ((lane >> 4) << 3) + (lane & 7);
        uint32_t addr =
            bbase + SWZ(rowb * 128 + ks * 32 + (((lane >> 3) & 1) << 4));
        asm volatile(
            "ldmatrix.sync.aligned.m8n8.x4.shared.b16 {%0,%1,%2,%3}, [%4];"
            : "=r"(br[2 * np][0]), "=r"(br[2 * np][1]),
              "=r"(br[2 * np + 1][0]), "=r"(br[2 * np + 1][1])
            : "r"(addr));
      }
#pragma unroll
      for (int mt = 0; mt < 4; mt++)
#pragma unroll
        for (int nt = 0; nt < 4; nt++) {
          asm volatile(
              "mma.sync.aligned.m16n8k16.row.col.f32.f16.f16.f32 "
              "{%0,%1,%2,%3}, {%4,%5,%6,%7}, {%8,%9}, {%0,%1,%2,%3};"
              : "+f"(acc[mt][nt][0]), "+f"(acc[mt][nt][1]),
                "+f"(acc[mt][nt][2]), "+f"(acc[mt][nt][3])
              : "r"(ar[mt][0]), "r"(ar[mt][1]), "r"(ar[mt][2]),
                "r"(ar[mt][3]), "r"(br[nt][0]), "r"(br[nt][1]));
        }
    }
  }

  // epilogue
  float* ob = out + (size_t)bh * 16384;
#pragma unroll
  for (int mt = 0; mt < 4; mt++) {
    int row0 = m0 + mt * 16 + (lane >> 2);
#pragma unroll
    for (int nt = 0; nt < 4; nt++) {
      int n = n0 + nt * 8 + 2 * (lane & 3);
      *(float2*)&ob[row0 * 128 + n] =
          make_float2(acc[mt][nt][0], acc[mt][nt][1]);
      *(float2*)&ob[(row0 + 8) * 128 + n] =
          make_float2(acc[mt][nt][2], acc[mt][nt][3]);
    }
  }
}

extern "C" void kernel_launch(void* const* d_in, const int* in_sizes, int n_in,
                              void* d_out, int out_size) {
  (void)in_sizes;
  (void)n_in;
  (void)out_size;
  const float* x = (const float*)d_in[0];
  const float* Woff = (const float*)d_in[1];
  const float* boff = (const float*)d_in[2];
  const float* Wm = (const float*)d_in[3];
  const float* bias = (const float*)d_in[4];
  float* out = (float*)d_out;

  const int smem_bytes = 3 * 32768 + 1024;
  cudaFuncSetAttribute(gemm_kernel, cudaFuncAttributeMaxDynamicSharedMemorySize,
                       smem_bytes);

  offsets_kernel<<<1024, 128>>>(x, Woff, boff);
  sample_kernel<<<1024, 256>>>();
  wprep_kernel<<<2592, 256>>>(Wm);
  gemm_kernel<<<1024, 256, smem_bytes>>>(bias, out);
}

// round 9
// speedup vs baseline: 1.3367x; 1.1630x over previous
#include <cuda_runtime.h>
#include <cuda_fp16.h>
#include <cstdint>

// x:(8,128,128,64) Woff:(3,3,64,18) boff:(18) W:(3,3,576,128)->(5184,128) b:(128)
// out:(8,128,128,128) f32

#define CHUNKS 81  // 5184/64; chunk q=(tap=q/9, ts=q%9), 64 channels

__device__ __half g_samp[8 * 128 * 128 * 9 * 64];  // (pixel, ts, c) 151MB
__device__ __half g_wt[CHUNKS * 128 * 64];         // [q][n][c] K-major

__device__ __forceinline__ uint32_t smem_u32(const void* p) {
  uint32_t a;
  asm("{ .reg .u64 t; cvta.to.shared.u64 t, %1; cvt.u32.u64 %0, t; }"
      : "=r"(a) : "l"(p));
  return a;
}

#define SWZ(o) ((o) ^ (((o) >> 3) & 0x70))
#define FMA2(d, a, bb) \
  asm("fma.rn.f32x2 %0, %1, %2, %0;" : "+l"(d) : "l"(a), "l"(bb))

// ------------------------------------------------------------------
// K1: fused offsets conv3x3 (FFMA2, smem-resident result) + bilinear
// sampling of this row -> g_samp fp16. One block per (b,h) row, 256 thr.
// ------------------------------------------------------------------
__global__ __launch_bounds__(256) void offsample_kernel(
    const float* __restrict__ x, const float* __restrict__ Woff,
    const float* __restrict__ boff) {
  __shared__ float xs[3][128][20];
  __shared__ float wofs[9][16][18];
  __shared__ float soff[128][18];

  const int tid = threadIdx.x;
  const int bh = blockIdx.x;
  const int b = bh >> 7, h = bh & 127;
  const int w = tid & 127;  // pixel for offsets phase (tid<128 active)

  unsigned long long acc2[9];
#pragma unroll
  for (int o = 0; o < 9; o++) acc2[o] = 0ull;

#pragma unroll 1
  for (int cc = 0; cc < 64; cc += 16) {
    // fill xs (3 rows x 128 w x 16 c) with all 256 threads
    for (int fid = tid; fid < 1536; fid += 256) {
      int r = fid / 512;
      int rem = fid - r * 512;
      int ww = rem >> 2;
      int cq = (rem & 3) * 4;
      int y = h + r - 1;
      float4 v = make_float4(0.f, 0.f, 0.f, 0.f);
      if ((unsigned)y < 128u)
        v = *(const float4*)&x[(((b * 128 + y) * 128 + ww) * 64) + cc + cq];
      *(float4*)&xs[r][ww][cq] = v;
    }
    for (int idx = tid; idx < 9 * 16 * 18; idx += 256) {
      int rs = idx / 288;
      ((float*)wofs)[idx] = Woff[idx + rs * 864 + cc * 18];
    }
    __syncthreads();

    if (tid < 128) {
#pragma unroll 1
      for (int rs = 0; rs < 9; rs++) {
        int r = rs / 3;
        int s = rs - r * 3;
        int wp = w + s - 1;
        if ((unsigned)wp < 128u) {
          float4 q0 = *(const float4*)&xs[r][wp][0];
          float4 q1 = *(const float4*)&xs[r][wp][4];
          float4 q2 = *(const float4*)&xs[r][wp][8];
          float4 q3 = *(const float4*)&xs[r][wp][12];
          float xv[16] = {q0.x, q0.y, q0.z, q0.w, q1.x, q1.y, q1.z, q1.w,
                          q2.x, q2.y, q2.z, q2.w, q3.x, q3.y, q3.z, q3.w};
#pragma unroll
          for (int c = 0; c < 16; c++) {
            unsigned long long ad;
            asm("mov.b64 %0, {%1, %1};" : "=l"(ad) : "f"(xv[c]));
#pragma unroll
            for (int op = 0; op < 9; op++) {
              unsigned long long bp =
                  *(const unsigned long long*)&wofs[rs][c][2 * op];
              FMA2(acc2[op], ad, bp);
            }
          }
        }
      }
    }
    __syncthreads();
  }

  if (tid < 128) {
#pragma unroll
    for (int op = 0; op < 9; op++) {
      float lo, hi;
      asm("mov.b64 {%0, %1}, %2;" : "=f"(lo), "=f"(hi) : "l"(acc2[op]));
      soff[w][2 * op] = lo + boff[2 * op];
      soff[w][2 * op + 1] = hi + boff[2 * op + 1];
    }
  }
  __syncthreads();

  // ---- sampling phase: 8 warps, warp handles pixels p = warp, warp+8, ...
  const int warp = tid >> 5, lane = tid & 31;
  const float* xb = x + ((size_t)b << 20);
  const int cl = 2 * lane;

  for (int p = warp; p < 128; p += 8) {
    const int pixbase = (bh * 128 + p) * 9;
#pragma unroll 3
    for (int ts = 0; ts < 9; ts++) {
      float ox = soff[p][2 * ts];
      float oy = soff[p][2 * ts + 1];
      float lx = (float)(p + (ts % 3) - 1) + ox;
      float ly = (float)(h + (ts / 3) - 1) + oy;
      lx = fminf(fmaxf(lx, 0.f), 127.f);
      ly = fminf(fmaxf(ly, 0.f), 127.f);
      float x0f = floorf(lx), y0f = floorf(ly);
      int xi0 = (int)x0f, yi0 = (int)y0f;
      int xi1 = min(xi0 + 1, 127), yi1 = min(yi0 + 1, 127);
      float dx0 = lx - x0f, dy0 = ly - y0f;
      float dx1 = (float)xi1 - lx, dy1 = (float)yi1 - ly;
      float wa = dx1 * dy1, wb = dx1 * dy0, wc = dx0 * dy1, wd = dx0 * dy0;

      int r0 = yi0 << 13, r1 = yi1 << 13;  // y * 128*64 (floats)
      int cx0 = xi0 << 6, cx1 = xi1 << 6;
      float2 Ia = *(const float2*)&xb[r0 + cx0 + cl];
      float2 Ib = *(const float2*)&xb[r1 + cx0 + cl];
      float2 Ic = *(const float2*)&xb[r0 + cx1 + cl];
      float2 Id = *(const float2*)&xb[r1 + cx1 + cl];
      float vx = wa * Ia.x + wb * Ib.x + wc * Ic.x + wd * Id.x;
      float vy = wa * Ia.y + wb * Ib.y + wc * Ic.y + wd * Id.y;
      *(__half2*)&g_samp[(size_t)(pixbase + ts) * 64 + cl] =
          __floats2half2_rn(vx, vy);
    }
  }
}

// ------------------------------------------------------------------
// K2: W (5184,128) -> fp16 [q][n][c]
// ------------------------------------------------------------------
__global__ __launch_bounds__(256) void wprep_kernel(const float* __restrict__ Wm) {
  int i = blockIdx.x * 256 + threadIdx.x;
  int c = i & 63;
  int n = (i >> 6) & 127;
  int q = i >> 13;
  g_wt[i] = __float2half(Wm[(q * 64 + c) * 128 + n]);
}

// ------------------------------------------------------------------
// K3: fp16 mma.sync implicit GEMM. One block per (b,h) row.
// M=128,N=128,K=5184. 8 warps m64xn32. 3-stage cp.async, 1 sync/chunk.
// ------------------------------------------------------------------
__global__ __launch_bounds__(256, 2) void gemm_kernel(
    const float* __restrict__ bias, float* __restrict__ out) {
  extern __shared__ __align__(16) char smraw[];
  const uint32_t sb = smem_u32(smraw);
  const uint32_t tiles = (sb + 1023u) & ~1023u;

  const int tid = threadIdx.x, lane = tid & 31, wid = tid >> 5;
  const int bh = blockIdx.x;
  const int b = bh >> 7, h = bh & 127;

  auto load_chunk = [&](int q, int st) {
    int tap = q / 9, ts = q - tap * 9;
    int r = tap / 3, s = tap - r * 3;
    int y = h + r - 1;
    uint32_t abase = tiles + (uint32_t)st * 32768u;
    uint32_t bbase = abase + 16384u;
#pragma unroll
    for (int j = 0; j < 4; j++) {
      int seg = j * 256 + tid;
      int arow = seg >> 3, acol = seg & 7;
      int wp = arow + s - 1;
      bool ok = ((unsigned)y < 128u) && ((unsigned)wp < 128u);
      const __half* src =
          ok ? g_samp + ((((size_t)((b * 128 + y) * 128 + wp)) * 9 + ts) * 64 +
                         acol * 8)
             : g_samp;
      uint32_t dst = abase + SWZ(arow * 128 + acol * 16);
      int sz = ok ? 16 : 0;
      asm volatile("cp.async.cg.shared.global [%0], [%1], 16, %2;" ::"r"(dst),
                   "l"(src), "r"(sz));
    }
#pragma unroll
    for (int j = 0; j < 4; j++) {
      int seg = j * 256 + tid;
      int brow = seg >> 3, bcol = seg & 7;
      const __half* src = g_wt + ((size_t)q * 8192 + brow * 64 + bcol * 8);
      uint32_t dst = bbase + SWZ(brow * 128 + bcol * 16);
      asm volatile("cp.async.cg.shared.global [%0], [%1], 16;" ::"r"(dst),
                   "l"(src));
    }
    asm volatile("cp.async.commit_group;" ::);
  };

  const int m0 = (wid & 1) * 64;
  const int n0 = (wid >> 1) * 32;

  float acc[4][4][4];
#pragma unroll
  for (int nt = 0; nt < 4; nt++) {
    int n = n0 + nt * 8 + 2 * (lane & 3);
    float b0 = bias[n], b1 = bias[n + 1];
#pragma unroll
    for (int mt = 0; mt < 4; mt++) {
      acc[mt][nt][0] = b0;
      acc[mt][nt][1] = b1;
      acc[mt][nt][2] = b0;
      acc[mt][nt][3] = b1;
    }
  }

  load_chunk(0, 0);
  load_chunk(1, 1);

  for (int c = 0; c < CHUNKS; c++) {
    const int st = c % 3;
    if (c + 1 < CHUNKS)
      asm volatile("cp.async.wait_group 1;" ::);
    else
      asm volatile("cp.async.wait_group 0;" ::);
    __syncthreads();
    if (c + 2 < CHUNKS) load_chunk(c + 2, (c + 2) % 3);

    const uint32_t abase = tiles + (uint32_t)st * 32768u;
    const uint32_t bbase = abase + 16384u;
#pragma unroll
    for (int ks = 0; ks < 4; ks++) {
      uint32_t ar[4][4], br[4][2];
#pragma unroll
      for (int mt = 0; mt < 4; mt++) {
        int row = m0 + mt * 16 + (lane & 15);
        uint32_t addr = abase + SWZ(row * 128 + ks * 32 + ((lane >> 4) << 4));
        asm volatile(
            "ldmatrix.sync.aligned.m8n8.x4.shared.b16 {%0,%1,%2,%3}, [%4];"
            : "=r"(ar[mt][0]), "=r"(ar[mt][1]), "=r"(ar[mt][2]),
              "=r"(ar[mt][3])
            : "r"(addr));
      }
#pragma unroll
      for (int np = 0; np < 2; np++) {
        int rowb = n0 + np * 16 + ((lane >> 4) << 3) + (lane & 7);
        uint32_t addr =
            bbase + SWZ(rowb * 128 + ks * 32 + (((lane >> 3) & 1) << 4));
        asm volatile(
            "ldmatrix.sync.aligned.m8n8.x4.shared.b16 {%0,%1,%2,%3}, [%4];"
            : "=r"(br[2 * np][0]), "=r"(br[2 * np][1]),
              "=r"(br[2 * np + 1][0]), "=r"(br[2 * np + 1][1])
            : "r"(addr));
      }
#pragma unroll
      for (int mt = 0; mt < 4; mt++)
#pragma unroll
        for (int nt = 0; nt < 4; nt++) {
          asm volatile(
              "mma.sync.aligned.m16n8k16.row.col.f32.f16.f16.f32 "
              "{%0,%1,%2,%3}, {%4,%5,%6,%7}, {%8,%9}, {%0,%1,%2,%3};"
              : "+f"(acc[mt][nt][0]), "+f"(acc[mt][nt][1]),
                "+f"(acc[mt][nt][2]), "+f"(acc[mt][nt][3])
              : "r"(ar[mt][0]), "r"(ar[mt][1]), "r"(ar[mt][2]),
                "r"(ar[mt][3]), "r"(br[nt][0]), "r"(br[nt][1]));
        }
    }
  }

  // epilogue
  float* ob = out + (size_t)bh * 16384;
#pragma unroll
  for (int mt = 0; mt < 4; mt++) {
    int row0 = m0 + mt * 16 + (lane >> 2);
#pragma unroll
    for (int nt = 0; nt < 4; nt++) {
      int n = n0 + nt * 8 + 2 * (lane & 3);
      *(float2*)&ob[row0 * 128 + n] =
          make_float2(acc[mt][nt][0], acc[mt][nt][1]);
      *(float2*)&ob[(row0 + 8) * 128 + n] =
          make_float2(acc[mt][nt][2], acc[mt][nt][3]);
    }
  }
}

extern "C" void kernel_launch(void* const* d_in, const int* in_sizes, int n_in,
                              void* d_out, int out_size) {
  (void)in_sizes;
  (void)n_in;
  (void)out_size;
  const float* x = (const float*)d_in[0];
  const float* Woff = (const float*)d_in[1];
  const float* boff = (const float*)d_in[2];
  const float* Wm = (const float*)d_in[3];
  const float* bias = (const float*)d_in[4];
  float* out = (float*)d_out;

  const int smem_bytes = 3 * 32768 + 1024;
  cudaFuncSetAttribute(gemm_kernel, cudaFuncAttributeMaxDynamicSharedMemorySize,
                       smem_bytes);

  offsample_kernel<<<1024, 256>>>(x, Woff, boff);
  wprep_kernel<<<2592, 256>>>(Wm);
  gemm_kernel<<<1024, 256, smem_bytes>>>(bias, out);
}

// round 10
// speedup vs baseline: 1.3458x; 1.0068x over previous
#include <cuda_runtime.h>
#include <cuda_fp16.h>
#include <cstdint>

// x:(8,128,128,64) Woff:(3,3,64,18) boff:(18) W:(3,3,576,128)->(5184,128) b:(128)
// out:(8,128,128,128) f32

#define CHUNKS 81  // 5184/64; chunk q=(tap=q/9, ts=q%9), 64 channels

__device__ __half g_samp[8 * 128 * 128 * 9 * 64];  // (pixel, ts, c) 151MB
__device__ __half g_wt[CHUNKS * 128 * 64];         // [q][n][c] K-major

__device__ __forceinline__ uint32_t smem_u32(const void* p) {
  uint32_t a;
  asm("{ .reg .u64 t; cvta.to.shared.u64 t, %1; cvt.u32.u64 %0, t; }"
      : "=r"(a) : "l"(p));
  return a;
}

#define SWZ(o) ((o) ^ (((o) >> 3) & 0x70))
#define FMA2(d, a, bb) \
  asm("fma.rn.f32x2 %0, %1, %2, %0;" : "+l"(d) : "l"(a), "l"(bb))

// ------------------------------------------------------------------
// K1: fused offsets conv3x3 + bilinear sampling. One block per (b,h)
// row, 256 threads. Conv work split across both halves by rs subset:
// tid<128 -> rs 0..4, tid>=128 -> rs 5..8 (same pixel w = tid&127).
// ------------------------------------------------------------------
__global__ __launch_bounds__(256) void offsample_kernel(
    const float* __restrict__ x, const float* __restrict__ Woff,
    const float* __restrict__ boff) {
  __shared__ float xs[3][128][20];
  __shared__ float wofs[9][16][18];
  __shared__ float soff[128][18];

  const int tid = threadIdx.x;
  const int bh = blockIdx.x;
  const int b = bh >> 7, h = bh & 127;
  const int w = tid & 127;
  const int rs0 = (tid < 128) ? 0 : 5;
  const int rs1 = (tid < 128) ? 5 : 9;

  unsigned long long acc2[9];
#pragma unroll
  for (int o = 0; o < 9; o++) acc2[o] = 0ull;

#pragma unroll 1
  for (int cc = 0; cc < 64; cc += 16) {
    // fill xs (3 rows x 128 w x 16 c) with all 256 threads
    for (int fid = tid; fid < 1536; fid += 256) {
      int r = fid / 512;
      int rem = fid - r * 512;
      int ww = rem >> 2;
      int cq = (rem & 3) * 4;
      int y = h + r - 1;
      float4 v = make_float4(0.f, 0.f, 0.f, 0.f);
      if ((unsigned)y < 128u)
        v = *(const float4*)&x[(((b * 128 + y) * 128 + ww) * 64) + cc + cq];
      *(float4*)&xs[r][ww][cq] = v;
    }
    for (int idx = tid; idx < 9 * 16 * 18; idx += 256) {
      int rs = idx / 288;
      ((float*)wofs)[idx] = Woff[idx + rs * 864 + cc * 18];
    }
    __syncthreads();

#pragma unroll 1
    for (int rs = rs0; rs < rs1; rs++) {
      int r = rs / 3;
      int s = rs - r * 3;
      int wp = w + s - 1;
      if ((unsigned)wp < 128u) {
        float4 q0 = *(const float4*)&xs[r][wp][0];
        float4 q1 = *(const float4*)&xs[r][wp][4];
        float4 q2 = *(const float4*)&xs[r][wp][8];
        float4 q3 = *(const float4*)&xs[r][wp][12];
        float xv[16] = {q0.x, q0.y, q0.z, q0.w, q1.x, q1.y, q1.z, q1.w,
                        q2.x, q2.y, q2.z, q2.w, q3.x, q3.y, q3.z, q3.w};
#pragma unroll
        for (int c = 0; c < 16; c++) {
          unsigned long long ad;
          asm("mov.b64 %0, {%1, %1};" : "=l"(ad) : "f"(xv[c]));
#pragma unroll
          for (int op = 0; op < 9; op++) {
            unsigned long long bp =
                *(const unsigned long long*)&wofs[rs][c][2 * op];
            FMA2(acc2[op], ad, bp);
          }
        }
      }
    }
    __syncthreads();
  }

  // combine partials: upper half dumps into dead xs scratch
  float* scr = &xs[0][0][0];
  if (tid >= 128) {
#pragma unroll
    for (int op = 0; op < 9; op++) {
      float lo, hi;
      asm("mov.b64 {%0, %1}, %2;" : "=f"(lo), "=f"(hi) : "l"(acc2[op]));
      scr[w * 18 + 2 * op] = lo;
      scr[w * 18 + 2 * op + 1] = hi;
    }
  }
  __syncthreads();
  if (tid < 128) {
#pragma unroll
    for (int op = 0; op < 9; op++) {
      float lo, hi;
      asm("mov.b64 {%0, %1}, %2;" : "=f"(lo), "=f"(hi) : "l"(acc2[op]));
      soff[w][2 * op] = lo + scr[w * 18 + 2 * op] + boff[2 * op];
      soff[w][2 * op + 1] = hi + scr[w * 18 + 2 * op + 1] + boff[2 * op + 1];
    }
  }
  __syncthreads();

  // ---- sampling phase: 8 warps, warp handles pixels p = warp, warp+8, ...
  const int warp = tid >> 5, lane = tid & 31;
  const float* xb = x + ((size_t)b << 20);
  const int cl = 2 * lane;

  for (int p = warp; p < 128; p += 8) {
    const int pixbase = (bh * 128 + p) * 9;
#pragma unroll 3
    for (int ts = 0; ts < 9; ts++) {
      float ox = soff[p][2 * ts];
      float oy = soff[p][2 * ts + 1];
      float lx = (float)(p + (ts % 3) - 1) + ox;
      float ly = (float)(h + (ts / 3) - 1) + oy;
      lx = fminf(fmaxf(lx, 0.f), 127.f);
      ly = fminf(fmaxf(ly, 0.f), 127.f);
      float x0f = floorf(lx), y0f = floorf(ly);
      int xi0 = (int)x0f, yi0 = (int)y0f;
      int xi1 = min(xi0 + 1, 127), yi1 = min(yi0 + 1, 127);
      float dx0 = lx - x0f, dy0 = ly - y0f;
      float dx1 = (float)xi1 - lx, dy1 = (float)yi1 - ly;
      float wa = dx1 * dy1, wb = dx1 * dy0, wc = dx0 * dy1, wd = dx0 * dy0;

      int r0 = yi0 << 13, r1 = yi1 << 13;  // y * 128*64 (floats)
      int cx0 = xi0 << 6, cx1 = xi1 << 6;
      float2 Ia = *(const float2*)&xb[r0 + cx0 + cl];
      float2 Ib = *(const float2*)&xb[r1 + cx0 + cl];
      float2 Ic = *(const float2*)&xb[r0 + cx1 + cl];
      float2 Id = *(const float2*)&xb[r1 + cx1 + cl];
      float vx = wa * Ia.x + wb * Ib.x + wc * Ic.x + wd * Id.x;
      float vy = wa * Ia.y + wb * Ib.y + wc * Ic.y + wd * Id.y;
      *(__half2*)&g_samp[(size_t)(pixbase + ts) * 64 + cl] =
          __floats2half2_rn(vx, vy);
    }
  }
}

// ------------------------------------------------------------------
// K2: W (5184,128) -> fp16 [q][n][c]
// ------------------------------------------------------------------
__global__ __launch_bounds__(256) void wprep_kernel(const float* __restrict__ Wm) {
  int i = blockIdx.x * 256 + threadIdx.x;
  int c = i & 63;
  int n = (i >> 6) & 127;
  int q = i >> 13;
  g_wt[i] = __float2half(Wm[(q * 64 + c) * 128 + n]);
}

// ------------------------------------------------------------------
// K3: fp16 mma.sync implicit GEMM. One block per (b,h) row.
// M=128,N=128,K=5184. 8 warps m64xn32. 3-stage cp.async, 1 sync/chunk.
// ------------------------------------------------------------------
__global__ __launch_bounds__(256, 2) void gemm_kernel(
    const float* __restrict__ bias, float* __restrict__ out) {
  extern __shared__ __align__(16) char smraw[];
  const uint32_t sb = smem_u32(smraw);
  const uint32_t tiles = (sb + 1023u) & ~1023u;

  const int tid = threadIdx.x, lane = tid & 31, wid = tid >> 5;
  const int bh = blockIdx.x;
  const int b = bh >> 7, h = bh & 127;

  auto load_chunk = [&](int q, int st) {
    int tap = q / 9, ts = q - tap * 9;
    int r = tap / 3, s = tap - r * 3;
    int y = h + r - 1;
    uint32_t abase = tiles + (uint32_t)st * 32768u;
    uint32_t bbase = abase + 16384u;
#pragma unroll
    for (int j = 0; j < 4; j++) {
      int seg = j * 256 + tid;
      int arow = seg >> 3, acol = seg & 7;
      int wp = arow + s - 1;
      bool ok = ((unsigned)y < 128u) && ((unsigned)wp < 128u);
      const __half* src =
          ok ? g_samp + ((((size_t)((b * 128 + y) * 128 + wp)) * 9 + ts) * 64 +
                         acol * 8)
             : g_samp;
      uint32_t dst = abase + SWZ(arow * 128 + acol * 16);
      int sz = ok ? 16 : 0;
      asm volatile("cp.async.cg.shared.global [%0], [%1], 16, %2;" ::"r"(dst),
                   "l"(src), "r"(sz));
    }
#pragma unroll
    for (int j = 0; j < 4; j++) {
      int seg = j * 256 + tid;
      int brow = seg >> 3, bcol = seg & 7;
      const __half* src = g_wt + ((size_t)q * 8192 + brow * 64 + bcol * 8);
      uint32_t dst = bbase + SWZ(brow * 128 + bcol * 16);
      asm volatile("cp.async.cg.shared.global [%0], [%1], 16;" ::"r"(dst),
                   "l"(src));
    }
    asm volatile("cp.async.commit_group;" ::);
  };

  const int m0 = (wid & 1) * 64;
  const int n0 = (wid >> 1) * 32;

  float acc[4][4][4];
#pragma unroll
  for (int nt = 0; nt < 4; nt++) {
    int n = n0 + nt * 8 + 2 * (lane & 3);
    float b0 = bias[n], b1 = bias[n + 1];
#pragma unroll
    for (int mt = 0; mt < 4; mt++) {
      acc[mt][nt][0] = b0;
      acc[mt][nt][1] = b1;
      acc[mt][nt][2] = b0;
      acc[mt][nt][3] = b1;
    }
  }

  load_chunk(0, 0);
  load_chunk(1, 1);

  for (int c = 0; c < CHUNKS; c++) {
    const int st = c % 3;
    if (c + 1 < CHUNKS)
      asm volatile("cp.async.wait_group 1;" ::);
    else
      asm volatile("cp.async.wait_group 0;" ::);
    __syncthreads();
    if (c + 2 < CHUNKS) load_chunk(c + 2, (c + 2) % 3);

    const uint32_t abase = tiles + (uint32_t)st * 32768u;
    const uint32_t bbase = abase + 16384u;
#pragma unroll
    for (int ks = 0; ks < 4; ks++) {
      uint32_t ar[4][4], br[4][2];
#pragma unroll
      for (int mt = 0; mt < 4; mt++) {
        int row = m0 + mt * 16 + (lane & 15);
        uint32_t addr = abase + SWZ(row * 128 + ks * 32 + ((lane >> 4) << 4));
        asm volatile(
            "ldmatrix.sync.aligned.m8n8.x4.shared.b16 {%0,%1,%2,%3}, [%4];"
            : "=r"(ar[mt][0]), "=r"(ar[mt][1]), "=r"(ar[mt][2]),
              "=r"(ar[mt][3])
            : "r"(addr));
      }
#pragma unroll
      for (int np = 0; np < 2; np++) {
        int rowb = n0 + np * 16 + ((lane >> 4) << 3) + (lane & 7);
        uint32_t addr =
            bbase + SWZ(rowb * 128 + ks * 32 + (((lane >> 3) & 1) << 4));
        asm volatile(
            "ldmatrix.sync.aligned.m8n8.x4.shared.b16 {%0,%1,%2,%3}, [%4];"
            : "=r"(br[2 * np][0]), "=r"(br[2 * np][1]),
              "=r"(br[2 * np + 1][0]), "=r"(br[2 * np + 1][1])
            : "r"(addr));
      }
#pragma unroll
      for (int mt = 0; mt < 4; mt++)
#pragma unroll
        for (int nt = 0; nt < 4; nt++) {
          asm volatile(
              "mma.sync.aligned.m16n8k16.row.col.f32.f16.f16.f32 "
              "{%0,%1,%2,%3}, {%4,%5,%6,%7}, {%8,%9}, {%0,%1,%2,%3};"
              : "+f"(acc[mt][nt][0]), "+f"(acc[mt][nt][1]),
                "+f"(acc[mt][nt][2]), "+f"(acc[mt][nt][3])
              : "r"(ar[mt][0]), "r"(ar[mt][1]), "r"(ar[mt][2]),
                "r"(ar[mt][3]), "r"(br[nt][0]), "r"(br[nt][1]));
        }
    }
  }

  // epilogue
  float* ob = out + (size_t)bh * 16384;
#pragma unroll
  for (int mt = 0; mt < 4; mt++) {
    int row0 = m0 + mt * 16 + (lane >> 2);
#pragma unroll
    for (int nt = 0; nt < 4; nt++) {
      int n = n0 + nt * 8 + 2 * (lane & 3);
      *(float2*)&ob[row0 * 128 + n] =
          make_float2(acc[mt][nt][0], acc[mt][nt][1]);
      *(float2*)&ob[(row0 + 8) * 128 + n] =
          make_float2(acc[mt][nt][2], acc[mt][nt][3]);
    }
  }
}

extern "C" void kernel_launch(void* const* d_in, const int* in_sizes, int n_in,
                              void* d_out, int out_size) {
  (void)in_sizes;
  (void)n_in;
  (void)out_size;
  const float* x = (const float*)d_in[0];
  const float* Woff = (const float*)d_in[1];
  const float* boff = (const float*)d_in[2];
  const float* Wm = (const float*)d_in[3];
  const float* bias = (const float*)d_in[4];
  float* out = (float*)d_out;

  const int smem_bytes = 3 * 32768 + 1024;
  cudaFuncSetAttribute(gemm_kernel, cudaFuncAttributeMaxDynamicSharedMemorySize,
                       smem_bytes);

  offsample_kernel<<<1024, 256>>>(x, Woff, boff);
  wprep_kernel<<<2592, 256>>>(Wm);
  gemm_kernel<<<1024, 256, smem_bytes>>>(bias, out);
}

// round 12
// speedup vs baseline: 1.3766x; 1.0229x over previous
#include <cuda_runtime.h>
#include <cuda_fp16.h>
#include <cstdint>

// x:(8,128,128,64) Woff:(3,3,64,18) boff:(18) W:(3,3,576,128)->(5184,128) b:(128)
// out:(8,128,128,128) f32

#define CHUNKS 81  // 5184/64; chunk q=(tap=q/9, ts=q%9), 64 channels

__device__ __half g_samp[8 * 128 * 128 * 9 * 64];  // (pixel, ts, c) 151MB
__device__ __half g_wt[CHUNKS * 128 * 64];         // [q][n][c] K-major

__device__ __forceinline__ uint32_t smem_u32(const void* p) {
  uint32_t a;
  asm("{ .reg .u64 t; cvta.to.shared.u64 t, %1; cvt.u32.u64 %0, t; }"
      : "=r"(a) : "l"(p));
  return a;
}

#define SWZ(o) ((o) ^ (((o) >> 3) & 0x70))
#define FMA2(d, a, bb) \
  asm("fma.rn.f32x2 %0, %1, %2, %0;" : "+l"(d) : "l"(a), "l"(bb))

// ------------------------------------------------------------------
// K1: fused offsets conv3x3 + bilinear sampling. One block per (b,h)
// row, 256 threads. Sampling: 2 tasks per warp (16-lane halves),
// float4 per lane -> half the instructions for the same bytes.
// ------------------------------------------------------------------
__global__ __launch_bounds__(256) void offsample_kernel(
    const float* __restrict__ x, const float* __restrict__ Woff,
    const float* __restrict__ boff) {
  __shared__ float xs[3][128][20];
  __shared__ float wofs[9][16][18];
  __shared__ float soff[128][18];

  const int tid = threadIdx.x;
  const int bh = blockIdx.x;
  const int b = bh >> 7, h = bh & 127;
  const int w = tid & 127;
  const int rs0 = (tid < 128) ? 0 : 5;
  const int rs1 = (tid < 128) ? 5 : 9;

  unsigned long long acc2[9];
#pragma unroll
  for (int o = 0; o < 9; o++) acc2[o] = 0ull;

#pragma unroll 1
  for (int cc = 0; cc < 64; cc += 16) {
    for (int fid = tid; fid < 1536; fid += 256) {
      int r = fid / 512;
      int rem = fid - r * 512;
      int ww = rem >> 2;
      int cq = (rem & 3) * 4;
      int y = h + r - 1;
      float4 v = make_float4(0.f, 0.f, 0.f, 0.f);
      if ((unsigned)y < 128u)
        v = *(const float4*)&x[(((b * 128 + y) * 128 + ww) * 64) + cc + cq];
      *(float4*)&xs[r][ww][cq] = v;
    }
    for (int idx = tid; idx < 9 * 16 * 18; idx += 256) {
      int rs = idx / 288;
      ((float*)wofs)[idx] = Woff[idx + rs * 864 + cc * 18];
    }
    __syncthreads();

#pragma unroll 1
    for (int rs = rs0; rs < rs1; rs++) {
      int r = rs / 3;
      int s = rs - r * 3;
      int wp = w + s - 1;
      if ((unsigned)wp < 128u) {
        float4 q0 = *(const float4*)&xs[r][wp][0];
        float4 q1 = *(const float4*)&xs[r][wp][4];
        float4 q2 = *(const float4*)&xs[r][wp][8];
        float4 q3 = *(const float4*)&xs[r][wp][12];
        float xv[16] = {q0.x, q0.y, q0.z, q0.w, q1.x, q1.y, q1.z, q1.w,
                        q2.x, q2.y, q2.z, q2.w, q3.x, q3.y, q3.z, q3.w};
#pragma unroll
        for (int c = 0; c < 16; c++) {
          unsigned long long ad;
          asm("mov.b64 %0, {%1, %1};" : "=l"(ad) : "f"(xv[c]));
#pragma unroll
          for (int op = 0; op < 9; op++) {
            unsigned long long bp =
                *(const unsigned long long*)&wofs[rs][c][2 * op];
            FMA2(acc2[op], ad, bp);
          }
        }
      }
    }
    __syncthreads();
  }

  // combine partials: upper half dumps into dead xs scratch
  float* scr = &xs[0][0][0];
  if (tid >= 128) {
#pragma unroll
    for (int op = 0; op < 9; op++) {
      float lo, hi;
      asm("mov.b64 {%0, %1}, %2;" : "=f"(lo), "=f"(hi) : "l"(acc2[op]));
      scr[w * 18 + 2 * op] = lo;
      scr[w * 18 + 2 * op + 1] = hi;
    }
  }
  __syncthreads();
  if (tid < 128) {
#pragma unroll
    for (int op = 0; op < 9; op++) {
      float lo, hi;
      asm("mov.b64 {%0, %1}, %2;" : "=f"(lo), "=f"(hi) : "l"(acc2[op]));
      soff[w][2 * op] = lo + scr[w * 18 + 2 * op] + boff[2 * op];
      soff[w][2 * op + 1] = hi + scr[w * 18 + 2 * op + 1] + boff[2 * op + 1];
    }
  }
  __syncthreads();

  // ---- sampling: 2 tasks per warp. lanes 0-15 task 2pi, 16-31 task 2pi+1.
  const int warp = tid >> 5, lane = tid & 31;
  const int half16 = lane >> 4, l16 = lane & 15;
  const int c4 = l16 * 4;  // 4 channels per lane
  const float* xb = x + ((size_t)b << 20);

#pragma unroll 4
  for (int it = 0; it < 72; it++) {
    int pi = warp + 8 * it;       // pair index 0..575
    int t = 2 * pi + half16;      // task 0..1151
    int p = t / 9;
    int ts = t - p * 9;
    float ox = soff[p][2 * ts];
    float oy = soff[p][2 * ts + 1];
    float lx = (float)(p + (ts % 3) - 1) + ox;
    float ly = (float)(h + (ts / 3) - 1) + oy;
    lx = fminf(fmaxf(lx, 0.f), 127.f);
    ly = fminf(fmaxf(ly, 0.f), 127.f);
    float x0f = floorf(lx), y0f = floorf(ly);
    int xi0 = (int)x0f, yi0 = (int)y0f;
    int xi1 = min(xi0 + 1, 127), yi1 = min(yi0 + 1, 127);
    float dx0 = lx - x0f, dy0 = ly - y0f;
    float dx1 = (float)xi1 - lx, dy1 = (float)yi1 - ly;
    float wa = dx1 * dy1, wb = dx1 * dy0, wc = dx0 * dy1, wd = dx0 * dy0;

    int r0 = yi0 << 13, r1 = yi1 << 13;  // y * 128*64 floats
    int cx0 = xi0 << 6, cx1 = xi1 << 6;
    float4 Ia = *(const float4*)&xb[r0 + cx0 + c4];
    float4 Ib = *(const float4*)&xb[r1 + cx0 + c4];
    float4 Ic = *(const float4*)&xb[r0 + cx1 + c4];
    float4 Id = *(const float4*)&xb[r1 + cx1 + c4];
    float4 v;
    v.x = wa * Ia.x + wb * Ib.x + wc * Ic.x + wd * Id.x;
    v.y = wa * Ia.y + wb * Ib.y + wc * Ic.y + wd * Id.y;
    v.z = wa * Ia.z + wb * Ib.z + wc * Ic.z + wd * Id.z;
    v.w = wa * Ia.w + wb * Ib.w + wc * Ic.w + wd * Id.w;

    union {
      __half2 hh[2];
      uint2 u;
    } cvt;
    cvt.hh[0] = __floats2half2_rn(v.x, v.y);
    cvt.hh[1] = __floats2half2_rn(v.z, v.w);
    *(uint2*)&g_samp[(size_t)((bh * 128 + p) * 9 + ts) * 64 + c4] = cvt.u;
  }
}

// ------------------------------------------------------------------
// K2: W (5184,128) -> fp16 [q][n][c]
// ------------------------------------------------------------------
__global__ __launch_bounds__(256) void wprep_kernel(const float* __restrict__ Wm) {
  int i = blockIdx.x * 256 + threadIdx.x;
  int c = i & 63;
  int n = (i >> 6) & 127;
  int q = i >> 13;
  g_wt[i] = __float2half(Wm[(q * 64 + c) * 128 + n]);
}

// ------------------------------------------------------------------
// K3: fp16 mma.sync implicit GEMM. One block per (b,h) row.
// M=128,N=128,K=5184. 8 warps m64xn32. 3-stage cp.async, 1 sync/chunk.
// ------------------------------------------------------------------
__global__ __launch_bounds__(256, 2) void gemm_kernel(
    const float* __restrict__ bias, float* __restrict__ out) {
  extern __shared__ __align__(16) char smraw[];
  const uint32_t sb = smem_u32(smraw);
  const uint32_t tiles = (sb + 1023u) & ~1023u;

  const int tid = threadIdx.x, lane = tid & 31, wid = tid >> 5;
  const int bh = blockIdx.x;
  const int b = bh >> 7, h = bh & 127;

  auto load_chunk = [&](int q, int st) {
    int tap = q / 9, ts = q - tap * 9;
    int r = tap / 3, s = tap - r * 3;
    int y = h + r - 1;
    uint32_t abase = tiles + (uint32_t)st * 32768u;
    uint32_t bbase = abase + 16384u;
#pragma unroll
    for (int j = 0; j < 4; j++) {
      int seg = j * 256 + tid;
      int arow = seg >> 3, acol = seg & 7;
      int wp = arow + s - 1;
      bool ok = ((unsigned)y < 128u) && ((unsigned)wp < 128u);
      const __half* src =
          ok ? g_samp + ((((size_t)((b * 128 + y) * 128 + wp)) * 9 + ts) * 64 +
                         acol * 8)
             : g_samp;
      uint32_t dst = abase + SWZ(arow * 128 + acol * 16);
      int sz = ok ? 16 : 0;
      asm volatile("cp.async.cg.shared.global [%0], [%1], 16, %2;" ::"r"(dst),
                   "l"(src), "r"(sz));
    }
#pragma unroll
    for (int j = 0; j < 4; j++) {
      int seg = j * 256 + tid;
      int brow = seg >> 3, bcol = seg & 7;
      const __half* src = g_wt + ((size_t)q * 8192 + brow * 64 + bcol * 8);
      uint32_t dst = bbase + SWZ(brow * 128 + bcol * 16);
      asm volatile("cp.async.cg.shared.global [%0], [%1], 16;" ::"r"(dst),
                   "l"(src));
    }
    asm volatile("cp.async.commit_group;" ::);
  };

  const int m0 = (wid & 1) * 64;
  const int n0 = (wid >> 1) * 32;

  float acc[4][4][4];
#pragma unroll
  for (int nt = 0; nt < 4; nt++) {
    int n = n0 + nt * 8 + 2 * (lane & 3);
    float b0 = bias[n], b1 = bias[n + 1];
#pragma unroll
    for (int mt = 0; mt < 4; mt++) {
      acc[mt][nt][0] = b0;
      acc[mt][nt][1] = b1;
      acc[mt][nt][2] = b0;
      acc[mt][nt][3] = b1;
    }
  }

  load_chunk(0, 0);
  load_chunk(1, 1);

  for (int c = 0; c < CHUNKS; c++) {
    const int st = c % 3;
    if (c + 1 < CHUNKS)
      asm volatile("cp.async.wait_group 1;" ::);
    else
      asm volatile("cp.async.wait_group 0;" ::);
    __syncthreads();
    if (c + 2 < CHUNKS) load_chunk(c + 2, (c + 2) % 3);

    const uint32_t abase = tiles + (uint32_t)st * 32768u;
    const uint32_t bbase = abase + 16384u;
#pragma unroll
    for (int ks = 0; ks < 4; ks++) {
      uint32_t ar[4][4], br[4][2];
#pragma unroll
      for (int mt = 0; mt < 4; mt++) {
        int row = m0 + mt * 16 + (lane & 15);
        uint32_t addr = abase + SWZ(row * 128 + ks * 32 + ((lane >> 4) << 4));
        asm volatile(
            "ldmatrix.sync.aligned.m8n8.x4.shared.b16 {%0,%1,%2,%3}, [%4];"
            : "=r"(ar[mt][0]), "=r"(ar[mt][1]), "=r"(ar[mt][2]),
              "=r"(ar[mt][3])
            : "r"(addr));
      }
#pragma unroll
      for (int np = 0; np < 2; np++) {
        int rowb = n0 + np * 16 + ((lane >> 4) << 3) + (lane & 7);
        uint32_t addr =
            bbase + SWZ(rowb * 128 + ks * 32 + (((lane >> 3) & 1) << 4));
        asm volatile(
            "ldmatrix.sync.aligned.m8n8.x4.shared.b16 {%0,%1,%2,%3}, [%4];"
            : "=r"(br[2 * np][0]), "=r"(br[2 * np][1]),
              "=r"(br[2 * np + 1][0]), "=r"(br[2 * np + 1][1])
            : "r"(addr));
      }
#pragma unroll
      for (int mt = 0; mt < 4; mt++)
#pragma unroll
        for (int nt = 0; nt < 4; nt++) {
          asm volatile(
              "mma.sync.aligned.m16n8k16.row.col.f32.f16.f16.f32 "
              "{%0,%1,%2,%3}, {%4,%5,%6,%7}, {%8,%9}, {%0,%1,%2,%3};"
              : "+f"(acc[mt][nt][0]), "+f"(acc[mt][nt][1]),
                "+f"(acc[mt][nt][2]), "+f"(acc[mt][nt][3])
              : "r"(ar[mt][0]), "r"(ar[mt][1]), "r"(ar[mt][2]),
                "r"(ar[mt][3]), "r"(br[nt][0]), "r"(br[nt][1]));
        }
    }
  }

  // epilogue
  float* ob = out + (size_t)bh * 16384;
#pragma unroll
  for (int mt = 0; mt < 4; mt++) {
    int row0 = m0 + mt * 16 + (lane >> 2);
#pragma unroll
    for (int nt = 0; nt < 4; nt++) {
      int n = n0 + nt * 8 + 2 * (lane & 3);
      *(float2*)&ob[row0 * 128 + n] =
          make_float2(acc[mt][nt][0], acc[mt][nt][1]);
      *(float2*)&ob[(row0 + 8) * 128 + n] =
          make_float2(acc[mt][nt][2], acc[mt][nt][3]);
    }
  }
}

extern "C" void kernel_launch(void* const* d_in, const int* in_sizes, int n_in,
                              void* d_out, int out_size) {
  (void)in_sizes;
  (void)n_in;
  (void)out_size;
  const float* x = (const float*)d_in[0];
  const float* Woff = (const float*)d_in[1];
  const float* boff = (const float*)d_in[2];
  const float* Wm = (const float*)d_in[3];
  const float* bias = (const float*)d_in[4];
  float* out = (float*)d_out;

  const int smem_bytes = 3 * 32768 + 1024;
  cudaFuncSetAttribute(gemm_kernel, cudaFuncAttributeMaxDynamicSharedMemorySize,
                       smem_bytes);

  offsample_kernel<<<1024, 256>>>(x, Woff, boff);
  wprep_kernel<<<2592, 256>>>(Wm);
  gemm_kernel<<<1024, 256, smem_bytes>>>(bias, out);
}

// round 13
// speedup vs baseline: 1.3827x; 1.0044x over previous
#include <cuda_runtime.h>
#include <cuda_fp16.h>
#include <cstdint>

// x:(8,128,128,64) Woff:(3,3,64,18) boff:(18) W:(3,3,576,128)->(5184,128) b:(128)
// out:(8,128,128,128) f32

#define CHUNKS 81  // 5184/64; chunk q=(tap=q/9, ts=q%9), 64 channels

__device__ __half g_xh[8 * 128 * 128 * 64];        // fp16 x (16.8MB)
__device__ __half g_samp[8 * 128 * 128 * 9 * 64];  // (pixel, ts, c) 151MB
__device__ __half g_wt[CHUNKS * 128 * 64];         // [q][n][c] K-major

__device__ __forceinline__ uint32_t smem_u32(const void* p) {
  uint32_t a;
  asm("{ .reg .u64 t; cvta.to.shared.u64 t, %1; cvt.u32.u64 %0, t; }"
      : "=r"(a) : "l"(p));
  return a;
}

#define SWZ(o) ((o) ^ (((o) >> 3) & 0x70))
#define FMA2(d, a, bb) \
  asm("fma.rn.f32x2 %0, %1, %2, %0;" : "+l"(d) : "l"(a), "l"(bb))

// ------------------------------------------------------------------
// K0: x -> fp16
// ------------------------------------------------------------------
__global__ __launch_bounds__(256) void xh_kernel(const float* __restrict__ x) {
  int i = blockIdx.x * 256 + threadIdx.x;  // 4.19M half2
  float2 v = *(const float2*)&x[2 * i];
  *(__half2*)&g_xh[2 * i] = __floats2half2_rn(v.x, v.y);
}

// ------------------------------------------------------------------
// K1: fused offsets conv3x3 + bilinear sampling. One block per (b,h)
// row, 256 threads. Sampling: 4 tasks per warp (8-lane groups), fp16
// gathers -> one 128B line per task-corner.
// ------------------------------------------------------------------
__global__ __launch_bounds__(256) void offsample_kernel(
    const float* __restrict__ x, const float* __restrict__ Woff,
    const float* __restrict__ boff) {
  __shared__ float xs[3][128][20];
  __shared__ float wofs[9][16][18];
  __shared__ float soff[128][18];

  const int tid = threadIdx.x;
  const int bh = blockIdx.x;
  const int b = bh >> 7, h = bh & 127;
  const int w = tid & 127;
  const int rs0 = (tid < 128) ? 0 : 5;
  const int rs1 = (tid < 128) ? 5 : 9;

  unsigned long long acc2[9];
#pragma unroll
  for (int o = 0; o < 9; o++) acc2[o] = 0ull;

#pragma unroll 1
  for (int cc = 0; cc < 64; cc += 16) {
    for (int fid = tid; fid < 1536; fid += 256) {
      int r = fid / 512;
      int rem = fid - r * 512;
      int ww = rem >> 2;
      int cq = (rem & 3) * 4;
      int y = h + r - 1;
      float4 v = make_float4(0.f, 0.f, 0.f, 0.f);
      if ((unsigned)y < 128u)
        v = *(const float4*)&x[(((b * 128 + y) * 128 + ww) * 64) + cc + cq];
      *(float4*)&xs[r][ww][cq] = v;
    }
    for (int idx = tid; idx < 9 * 16 * 18; idx += 256) {
      int rs = idx / 288;
      ((float*)wofs)[idx] = Woff[idx + rs * 864 + cc * 18];
    }
    __syncthreads();

#pragma unroll 1
    for (int rs = rs0; rs < rs1; rs++) {
      int r = rs / 3;
      int s = rs - r * 3;
      int wp = w + s - 1;
      if ((unsigned)wp < 128u) {
        float4 q0 = *(const float4*)&xs[r][wp][0];
        float4 q1 = *(const float4*)&xs[r][wp][4];
        float4 q2 = *(const float4*)&xs[r][wp][8];
        float4 q3 = *(const float4*)&xs[r][wp][12];
        float xv[16] = {q0.x, q0.y, q0.z, q0.w, q1.x, q1.y, q1.z, q1.w,
                        q2.x, q2.y, q2.z, q2.w, q3.x, q3.y, q3.z, q3.w};
#pragma unroll
        for (int c = 0; c < 16; c++) {
          unsigned long long ad;
          asm("mov.b64 %0, {%1, %1};" : "=l"(ad) : "f"(xv[c]));
#pragma unroll
          for (int op = 0; op < 9; op++) {
            unsigned long long bp =
                *(const unsigned long long*)&wofs[rs][c][2 * op];
            FMA2(acc2[op], ad, bp);
          }
        }
      }
    }
    __syncthreads();
  }

  float* scr = &xs[0][0][0];
  if (tid >= 128) {
#pragma unroll
    for (int op = 0; op < 9; op++) {
      float lo, hi;
      asm("mov.b64 {%0, %1}, %2;" : "=f"(lo), "=f"(hi) : "l"(acc2[op]));
      scr[w * 18 + 2 * op] = lo;
      scr[w * 18 + 2 * op + 1] = hi;
    }
  }
  __syncthreads();
  if (tid < 128) {
#pragma unroll
    for (int op = 0; op < 9; op++) {
      float lo, hi;
      asm("mov.b64 {%0, %1}, %2;" : "=f"(lo), "=f"(hi) : "l"(acc2[op]));
      soff[w][2 * op] = lo + scr[w * 18 + 2 * op] + boff[2 * op];
      soff[w][2 * op + 1] = hi + scr[w * 18 + 2 * op + 1] + boff[2 * op + 1];
    }
  }
  __syncthreads();

  // ---- sampling: 4 tasks per warp (8-lane groups), fp16 gathers.
  const int warp = tid >> 5, lane = tid & 31;
  const int quad = lane >> 3, l8 = lane & 7;
  const int c8 = l8 * 8;  // 8 channels per lane (16B)
  const __half* xb = g_xh + ((size_t)b << 20);

#pragma unroll 4
  for (int it = 0; it < 36; it++) {
    int t = 4 * (warp + 8 * it) + quad;  // task 0..1151
    int p = t / 9;
    int ts = t - p * 9;
    float ox = soff[p][2 * ts];
    float oy = soff[p][2 * ts + 1];
    float lx = (float)(p + (ts % 3) - 1) + ox;
    float ly = (float)(h + (ts / 3) - 1) + oy;
    lx = fminf(fmaxf(lx, 0.f), 127.f);
    ly = fminf(fmaxf(ly, 0.f), 127.f);
    float x0f = floorf(lx), y0f = floorf(ly);
    int xi0 = (int)x0f, yi0 = (int)y0f;
    int xi1 = min(xi0 + 1, 127), yi1 = min(yi0 + 1, 127);
    float dx0 = lx - x0f, dy0 = ly - y0f;
    float dx1 = (float)xi1 - lx, dy1 = (float)yi1 - ly;
    float wa = dx1 * dy1, wb = dx1 * dy0, wc = dx0 * dy1, wd = dx0 * dy0;

    int r0 = yi0 << 13, r1 = yi1 << 13;  // y * 128*64 halfs
    int cx0 = (xi0 << 6) + c8, cx1 = (xi1 << 6) + c8;

    union U {
      uint4 u;
      __half2 hh[4];
    };
    U Ia, Ib, Ic, Id, outv;
    Ia.u = *(const uint4*)&xb[r0 + cx0];
    Ib.u = *(const uint4*)&xb[r1 + cx0];
    Ic.u = *(const uint4*)&xb[r0 + cx1];
    Id.u = *(const uint4*)&xb[r1 + cx1];
#pragma unroll
    for (int j = 0; j < 4; j++) {
      float2 a = __half22float2(Ia.hh[j]);
      float2 bb = __half22float2(Ib.hh[j]);
      float2 c = __half22float2(Ic.hh[j]);
      float2 d = __half22float2(Id.hh[j]);
      outv.hh[j] = __floats2half2_rn(wa * a.x + wb * bb.x + wc * c.x + wd * d.x,
                                     wa * a.y + wb * bb.y + wc * c.y + wd * d.y);
    }
    *(uint4*)&g_samp[(size_t)((bh * 128 + p) * 9 + ts) * 64 + c8] = outv.u;
  }
}

// ------------------------------------------------------------------
// K2: W (5184,128) -> fp16 [q][n][c]
// ------------------------------------------------------------------
__global__ __launch_bounds__(256) void wprep_kernel(const float* __restrict__ Wm) {
  int i = blockIdx.x * 256 + threadIdx.x;
  int c = i & 63;
  int n = (i >> 6) & 127;
  int q = i >> 13;
  g_wt[i] = __float2half(Wm[(q * 64 + c) * 128 + n]);
}

// ------------------------------------------------------------------
// K3: fp16 mma.sync implicit GEMM. One block per (b,h) row.
// M=128,N=128,K=5184. 8 warps m64xn32. 3-stage cp.async, 1 sync/chunk.
// ------------------------------------------------------------------
__global__ __launch_bounds__(256, 2) void gemm_kernel(
    const float* __restrict__ bias, float* __restrict__ out) {
  extern __shared__ __align__(16) char smraw[];
  const uint32_t sb = smem_u32(smraw);
  const uint32_t tiles = (sb + 1023u) & ~1023u;

  const int tid = threadIdx.x, lane = tid & 31, wid = tid >> 5;
  const int bh = blockIdx.x;
  const int b = bh >> 7, h = bh & 127;

  auto load_chunk = [&](int q, int st) {
    int tap = q / 9, ts = q - tap * 9;
    int r = tap / 3, s = tap - r * 3;
    int y = h + r - 1;
    uint32_t abase = tiles + (uint32_t)st * 32768u;
    uint32_t bbase = abase + 16384u;
#pragma unroll
    for (int j = 0; j < 4; j++) {
      int seg = j * 256 + tid;
      int arow = seg >> 3, acol = seg & 7;
      int wp = arow + s - 1;
      bool ok = ((unsigned)y < 128u) && ((unsigned)wp < 128u);
      const __half* src =
          ok ? g_samp + ((((size_t)((b * 128 + y) * 128 + wp)) * 9 + ts) * 64 +
                         acol * 8)
             : g_samp;
      uint32_t dst = abase + SWZ(arow * 128 + acol * 16);
      int sz = ok ? 16 : 0;
      asm volatile("cp.async.cg.shared.global [%0], [%1], 16, %2;" ::"r"(dst),
                   "l"(src), "r"(sz));
    }
#pragma unroll
    for (int j = 0; j < 4; j++) {
      int seg = j * 256 + tid;
      int brow = seg >> 3, bcol = seg & 7;
      const __half* src = g_wt + ((size_t)q * 8192 + brow * 64 + bcol * 8);
      uint32_t dst = bbase + SWZ(brow * 128 + bcol * 16);
      asm volatile("cp.async.cg.shared.global [%0], [%1], 16;" ::"r"(dst),
                   "l"(src));
    }
    asm volatile("cp.async.commit_group;" ::);
  };

  const int m0 = (wid & 1) * 64;
  const int n0 = (wid >> 1) * 32;

  float acc[4][4][4];
#pragma unroll
  for (int nt = 0; nt < 4; nt++) {
    int n = n0 + nt * 8 + 2 * (lane & 3);
    float b0 = bias[n], b1 = bias[n + 1];
#pragma unroll
    for (int mt = 0; mt < 4; mt++) {
      acc[mt][nt][0] = b0;
      acc[mt][nt][1] = b1;
      acc[mt][nt][2] = b0;
      acc[mt][nt][3] = b1;
    }
  }

  load_chunk(0, 0);
  load_chunk(1, 1);

  for (int c = 0; c < CHUNKS; c++) {
    const int st = c % 3;
    if (c + 1 < CHUNKS)
      asm volatile("cp.async.wait_group 1;" ::);
    else
      asm volatile("cp.async.wait_group 0;" ::);
    __syncthreads();
    if (c + 2 < CHUNKS) load_chunk(c + 2, (c + 2) % 3);

    const uint32_t abase = tiles + (uint32_t)st * 32768u;
    const uint32_t bbase = abase + 16384u;
#pragma unroll
    for (int ks = 0; ks < 4; ks++) {
      uint32_t ar[4][4], br[4][2];
#pragma unroll
      for (int mt = 0; mt < 4; mt++) {
        int row = m0 + mt * 16 + (lane & 15);
        uint32_t addr = abase + SWZ(row * 128 + ks * 32 + ((lane >> 4) << 4));
        asm volatile(
            "ldmatrix.sync.aligned.m8n8.x4.shared.b16 {%0,%1,%2,%3}, [%4];"
            : "=r"(ar[mt][0]), "=r"(ar[mt][1]), "=r"(ar[mt][2]),
              "=r"(ar[mt][3])
            : "r"(addr));
      }
#pragma unroll
      for (int np = 0; np < 2; np++) {
        int rowb = n0 + np * 16 + ((lane >> 4) << 3) + (lane & 7);
        uint32_t addr =
            bbase + SWZ(rowb * 128 + ks * 32 + (((lane >> 3) & 1) << 4));
        asm volatile(
            "ldmatrix.sync.aligned.m8n8.x4.shared.b16 {%0,%1,%2,%3}, [%4];"
            : "=r"(br[2 * np][0]), "=r"(br[2 * np][1]),
              "=r"(br[2 * np + 1][0]), "=r"(br[2 * np + 1][1])
            : "r"(addr));
      }
#pragma unroll
      for (int mt = 0; mt < 4; mt++)
#pragma unroll
        for (int nt = 0; nt < 4; nt++) {
          asm volatile(
              "mma.sync.aligned.m16n8k16.row.col.f32.f16.f16.f32 "
              "{%0,%1,%2,%3}, {%4,%5,%6,%7}, {%8,%9}, {%0,%1,%2,%3};"
              : "+f"(acc[mt][nt][0]), "+f"(acc[mt][nt][1]),
                "+f"(acc[mt][nt][2]), "+f"(acc[mt][nt][3])
              : "r"(ar[mt][0]), "r"(ar[mt][1]), "r"(ar[mt][2]),
                "r"(ar[mt][3]), "r"(br[nt][0]), "r"(br[nt][1]));
        }
    }
  }

  // epilogue
  float* ob = out + (size_t)bh * 16384;
#pragma unroll
  for (int mt = 0; mt < 4; mt++) {
    int row0 = m0 + mt * 16 + (lane >> 2);
#pragma unroll
    for (int nt = 0; nt < 4; nt++) {
      int n = n0 + nt * 8 + 2 * (lane & 3);
      *(float2*)&ob[row0 * 128 + n] =
          make_float2(acc[mt][nt][0], acc[mt][nt][1]);
      *(float2*)&ob[(row0 + 8) * 128 + n] =
          make_float2(acc[mt][nt][2], acc[mt][nt][3]);
    }
  }
}

extern "C" void kernel_launch(void* const* d_in, const int* in_sizes, int n_in,
                              void* d_out, int out_size) {
  (void)in_sizes;
  (void)n_in;
  (void)out_size;
  const float* x = (const float*)d_in[0];
  const float* Woff = (const float*)d_in[1];
  const float* boff = (const float*)d_in[2];
  const float* Wm = (const float*)d_in[3];
  const float* bias = (const float*)d_in[4];
  float* out = (float*)d_out;

  const int smem_bytes = 3 * 32768 + 1024;
  cudaFuncSetAttribute(gemm_kernel, cudaFuncAttributeMaxDynamicSharedMemorySize,
                       smem_bytes);

  xh_kernel<<<16384, 256>>>(x);
  offsample_kernel<<<1024, 256>>>(x, Woff, boff);
  wprep_kernel<<<2592, 256>>>(Wm);
  gemm_kernel<<<1024, 256, smem_bytes>>>(bias, out);
}

// round 16
// speedup vs baseline: 1.3869x; 1.0030x over previous
#include <cuda_runtime.h>
#include <cuda_fp16.h>
#include <cstdint>

// x:(8,128,128,64) Woff:(3,3,64,18) boff:(18) W:(3,3,576,128)->(5184,128) b:(128)
// out:(8,128,128,128) f32

#define CHUNKS 81  // 5184/64; chunk q=(tap=q/9, ts=q%9), 64 channels

__device__ __half g_xh[8 * 128 * 128 * 64];        // fp16 x (16.8MB)
__device__ __half g_samp[8 * 128 * 128 * 9 * 64];  // (pixel, ts, c) 151MB
__device__ __half g_wt[CHUNKS * 128 * 64];         // [q][n][c] K-major

__device__ __forceinline__ uint32_t smem_u32(const void* p) {
  uint32_t a;
  asm("{ .reg .u64 t; cvta.to.shared.u64 t, %1; cvt.u32.u64 %0, t; }"
      : "=r"(a) : "l"(p));
  return a;
}

#define SWZ(o) ((o) ^ (((o) >> 3) & 0x70))
#define FMA2(d, a, bb) \
  asm("fma.rn.f32x2 %0, %1, %2, %0;" : "+l"(d) : "l"(a), "l"(bb))

// ------------------------------------------------------------------
// K0: prep = x->fp16 (16384 blocks) + W repack fp16 (2592 blocks)
// ------------------------------------------------------------------
__global__ __launch_bounds__(256) void prep_kernel(const float* __restrict__ x,
                                                   const float* __restrict__ Wm) {
  int bidx = blockIdx.x;
  if (bidx < 16384) {  // xh: 4.19M half2
    int i = bidx * 256 + threadIdx.x;
    float2 v = *(const float2*)&x[2 * i];
    *(__half2*)&g_xh[2 * i] = __floats2half2_rn(v.x, v.y);
  } else {  // wt: 663552 elems
    int i = (bidx - 16384) * 256 + threadIdx.x;
    int c = i & 63;
    int n = (i >> 6) & 127;
    int q = i >> 13;
    g_wt[i] = __float2half(Wm[(q * 64 + c) * 128 + n]);
  }
}

// ------------------------------------------------------------------
// K1: fused offsets conv3x3 (fp32 FFMA2, smem-resident) + bilinear
// sampling (fp16 gathers, 4 tasks/warp). One block per (b,h) row.
// ------------------------------------------------------------------
__global__ __launch_bounds__(256) void offsample_kernel(
    const float* __restrict__ x, const float* __restrict__ Woff,
    const float* __restrict__ boff) {
  __shared__ float xs[3][128][20];
  __shared__ float wofs[9][16][18];
  __shared__ float soff[128][18];

  const int tid = threadIdx.x;
  const int bh = blockIdx.x;
  const int b = bh >> 7, h = bh & 127;
  const int w = tid & 127;
  const int rs0 = (tid < 128) ? 0 : 5;
  const int rs1 = (tid < 128) ? 5 : 9;

  unsigned long long acc2[9];
#pragma unroll
  for (int o = 0; o < 9; o++) acc2[o] = 0ull;

#pragma unroll 1
  for (int cc = 0; cc < 64; cc += 16) {
    for (int fid = tid; fid < 1536; fid += 256) {
      int r = fid / 512;
      int rem = fid - r * 512;
      int ww = rem >> 2;
      int cq = (rem & 3) * 4;
      int y = h + r - 1;
      float4 v = make_float4(0.f, 0.f, 0.f, 0.f);
      if ((unsigned)y < 128u)
        v = *(const float4*)&x[(((b * 128 + y) * 128 + ww) * 64) + cc + cq];
      *(float4*)&xs[r][ww][cq] = v;
    }
    for (int idx = tid; idx < 9 * 16 * 18; idx += 256) {
      int rs = idx / 288;
      ((float*)wofs)[idx] = Woff[idx + rs * 864 + cc * 18];
    }
    __syncthreads();

#pragma unroll 1
    for (int rs = rs0; rs < rs1; rs++) {
      int r = rs / 3;
      int s = rs - r * 3;
      int wp = w + s - 1;
      if ((unsigned)wp < 128u) {
        float4 q0 = *(const float4*)&xs[r][wp][0];
        float4 q1 = *(const float4*)&xs[r][wp][4];
        float4 q2 = *(const float4*)&xs[r][wp][8];
        float4 q3 = *(const float4*)&xs[r][wp][12];
        float xv[16] = {q0.x, q0.y, q0.z, q0.w, q1.x, q1.y, q1.z, q1.w,
                        q2.x, q2.y, q2.z, q2.w, q3.x, q3.y, q3.z, q3.w};
#pragma unroll
        for (int c = 0; c < 16; c++) {
          unsigned long long ad;
          asm("mov.b64 %0, {%1, %1};" : "=l"(ad) : "f"(xv[c]));
#pragma unroll
          for (int op = 0; op < 9; op++) {
            unsigned long long bp =
                *(const unsigned long long*)&wofs[rs][c][2 * op];
            FMA2(acc2[op], ad, bp);
          }
        }
      }
    }
    __syncthreads();
  }

  float* scr = &xs[0][0][0];
  if (tid >= 128) {
#pragma unroll
    for (int op = 0; op < 9; op++) {
      float lo, hi;
      asm("mov.b64 {%0, %1}, %2;" : "=f"(lo), "=f"(hi) : "l"(acc2[op]));
      scr[w * 18 + 2 * op] = lo;
      scr[w * 18 + 2 * op + 1] = hi;
    }
  }
  __syncthreads();
  if (tid < 128) {
#pragma unroll
    for (int op = 0; op < 9; op++) {
      float lo, hi;
      asm("mov.b64 {%0, %1}, %2;" : "=f"(lo), "=f"(hi) : "l"(acc2[op]));
      soff[w][2 * op] = lo + scr[w * 18 + 2 * op] + boff[2 * op];
      soff[w][2 * op + 1] = hi + scr[w * 18 + 2 * op + 1] + boff[2 * op + 1];
    }
  }
  __syncthreads();

  // ---- sampling: 4 tasks per warp (8-lane groups), fp16 gathers.
  const int warp = tid >> 5, lane = tid & 31;
  const int quad = lane >> 3, l8 = lane & 7;
  const int c8 = l8 * 8;  // 8 channels per lane (16B)
  const __half* xb = g_xh + ((size_t)b << 20);

#pragma unroll 4
  for (int it = 0; it < 36; it++) {
    int t = 4 * (warp + 8 * it) + quad;  // task 0..1151
    int p = t / 9;
    int ts = t - p * 9;
    float ox = soff[p][2 * ts];
    float oy = soff[p][2 * ts + 1];
    float lx = (float)(p + (ts % 3) - 1) + ox;
    float ly = (float)(h + (ts / 3) - 1) + oy;
    lx = fminf(fmaxf(lx, 0.f), 127.f);
    ly = fminf(fmaxf(ly, 0.f), 127.f);
    float x0f = floorf(lx), y0f = floorf(ly);
    int xi0 = (int)x0f, yi0 = (int)y0f;
    int xi1 = min(xi0 + 1, 127), yi1 = min(yi0 + 1, 127);
    float dx0 = lx - x0f, dy0 = ly - y0f;
    float dx1 = (float)xi1 - lx, dy1 = (float)yi1 - ly;
    float wa = dx1 * dy1, wb = dx1 * dy0, wc = dx0 * dy1, wd = dx0 * dy0;

    int r0 = yi0 << 13, r1 = yi1 << 13;  // y * 128*64 halfs
    int cx0 = (xi0 << 6) + c8, cx1 = (xi1 << 6) + c8;

    union U {
      uint4 u;
      __half2 hh[4];
    };
    U Ia, Ib, Ic, Id, outv;
    Ia.u = *(const uint4*)&xb[r0 + cx0];
    Ib.u = *(const uint4*)&xb[r1 + cx0];
    Ic.u = *(const uint4*)&xb[r0 + cx1];
    Id.u = *(const uint4*)&xb[r1 + cx1];
#pragma unroll
    for (int j = 0; j < 4; j++) {
      float2 a = __half22float2(Ia.hh[j]);
      float2 bb = __half22float2(Ib.hh[j]);
      float2 c = __half22float2(Ic.hh[j]);
      float2 d = __half22float2(Id.hh[j]);
      outv.hh[j] =
          __floats2half2_rn(wa * a.x + wb * bb.x + wc * c.x + wd * d.x,
                            wa * a.y + wb * bb.y + wc * c.y + wd * d.y);
    }
    *(uint4*)&g_samp[(size_t)((bh * 128 + p) * 9 + ts) * 64 + c8] = outv.u;
  }
}

// ------------------------------------------------------------------
// K2: fp16 mma.sync implicit GEMM (proven 427us). One block per row.
// M=128,N=128,K=5184. 8 warps m64xn32. 3-stage cp.async, 1 sync/chunk.
// ------------------------------------------------------------------
__global__ __launch_bounds__(256, 2) void gemm_kernel(
    const float* __restrict__ bias, float* __restrict__ out) {
  extern __shared__ __align__(16) char smraw[];
  const uint32_t sb = smem_u32(smraw);
  const uint32_t tiles = (sb + 1023u) & ~1023u;

  const int tid = threadIdx.x, lane = tid & 31, wid = tid >> 5;
  const int bh = blockIdx.x;
  const int b = bh >> 7, h = bh & 127;

  auto load_chunk = [&](int q, int st) {
    int tap = q / 9, ts = q - tap * 9;
    int r = tap / 3, s = tap - r * 3;
    int y = h + r - 1;
    uint32_t abase = tiles + (uint32_t)st * 32768u;
    uint32_t bbase = abase + 16384u;
#pragma unroll
    for (int j = 0; j < 4; j++) {
      int seg = j * 256 + tid;
      int arow = seg >> 3, acol = seg & 7;
      int wp = arow + s - 1;
      bool ok = ((unsigned)y < 128u) && ((unsigned)wp < 128u);
      const __half* src =
          ok ? g_samp + ((((size_t)((b * 128 + y) * 128 + wp)) * 9 + ts) * 64 +
                         acol * 8)
             : g_samp;
      uint32_t dst = abase + SWZ(arow * 128 + acol * 16);
      int sz = ok ? 16 : 0;
      asm volatile("cp.async.cg.shared.global [%0], [%1], 16, %2;" ::"r"(dst),
                   "l"(src), "r"(sz));
    }
#pragma unroll
    for (int j = 0; j < 4; j++) {
      int seg = j * 256 + tid;
      int brow = seg >> 3, bcol = seg & 7;
      const __half* src = g_wt + ((size_t)q * 8192 + brow * 64 + bcol * 8);
      uint32_t dst = bbase + SWZ(brow * 128 + bcol * 16);
      asm volatile("cp.async.cg.shared.global [%0], [%1], 16;" ::"r"(dst),
                   "l"(src));
    }
    asm volatile("cp.async.commit_group;" ::);
  };

  const int m0 = (wid & 1) * 64;
  const int n0 = (wid >> 1) * 32;

  float acc[4][4][4];
#pragma unroll
  for (int nt = 0; nt < 4; nt++) {
    int n = n0 + nt * 8 + 2 * (lane & 3);
    float b0 = bias[n], b1 = bias[n + 1];
#pragma unroll
    for (int mt = 0; mt < 4; mt++) {
      acc[mt][nt][0] = b0;
      acc[mt][nt][1] = b1;
      acc[mt][nt][2] = b0;
      acc[mt][nt][3] = b1;
    }
  }

  load_chunk(0, 0);
  load_chunk(1, 1);

  for (int c = 0; c < CHUNKS; c++) {
    const int st = c % 3;
    if (c + 1 < CHUNKS)
      asm volatile("cp.async.wait_group 1;" ::);
    else
      asm volatile("cp.async.wait_group 0;" ::);
    __syncthreads();
    if (c + 2 < CHUNKS) load_chunk(c + 2, (c + 2) % 3);

    const uint32_t abase = tiles + (uint32_t)st * 32768u;
    const uint32_t bbase = abase + 16384u;
#pragma unroll
    for (int ks = 0; ks < 4; ks++) {
      uint32_t ar[4][4], br[4][2];
#pragma unroll
      for (int mt = 0; mt < 4; mt++) {
        int row = m0 + mt * 16 + (lane & 15);
        uint32_t addr = abase + SWZ(row * 128 + ks * 32 + ((lane >> 4) << 4));
        asm volatile(
            "ldmatrix.sync.aligned.m8n8.x4.shared.b16 {%0,%1,%2,%3}, [%4];"
            : "=r"(ar[mt][0]), "=r"(ar[mt][1]), "=r"(ar[mt][2]),
              "=r"(ar[mt][3])
            : "r"(addr));
      }
#pragma unroll
      for (int np = 0; np < 2; np++) {
        int rowb = n0 + np * 16 + ((lane >> 4) << 3) + (lane & 7);
        uint32_t addr =
            bbase + SWZ(rowb * 128 + ks * 32 + (((lane >> 3) & 1) << 4));
        asm volatile(
            "ldmatrix.sync.aligned.m8n8.x4.shared.b16 {%0,%1,%2,%3}, [%4];"
            : "=r"(br[2 * np][0]), "=r"(br[2 * np][1]),
              "=r"(br[2 * np + 1][0]), "=r"(br[2 * np + 1][1])
            : "r"(addr));
      }
#pragma unroll
      for (int mt = 0; mt < 4; mt++)
#pragma unroll
        for (int nt = 0; nt < 4; nt++) {
          asm volatile(
              "mma.sync.aligned.m16n8k16.row.col.f32.f16.f16.f32 "
              "{%0,%1,%2,%3}, {%4,%5,%6,%7}, {%8,%9}, {%0,%1,%2,%3};"
              : "+f"(acc[mt][nt][0]), "+f"(acc[mt][nt][1]),
                "+f"(acc[mt][nt][2]), "+f"(acc[mt][nt][3])
              : "r"(ar[mt][0]), "r"(ar[mt][1]), "r"(ar[mt][2]),
                "r"(ar[mt][3]), "r"(br[nt][0]), "r"(br[nt][1]));
        }
    }
  }

  float* ob = out + (size_t)bh * 16384;
#pragma unroll
  for (int mt = 0; mt < 4; mt++) {
    int row0 = m0 + mt * 16 + (lane >> 2);
#pragma unroll
    for (int nt = 0; nt < 4; nt++) {
      int n = n0 + nt * 8 + 2 * (lane & 3);
      *(float2*)&ob[row0 * 128 + n] =
          make_float2(acc[mt][nt][0], acc[mt][nt][1]);
      *(float2*)&ob[(row0 + 8) * 128 + n] =
          make_float2(acc[mt][nt][2], acc[mt][nt][3]);
    }
  }
}

extern "C" void kernel_launch(void* const* d_in, const int* in_sizes, int n_in,
                              void* d_out, int out_size) {
  (void)in_sizes;
  (void)n_in;
  (void)out_size;
  const float* x = (const float*)d_in[0];
  const float* Woff = (const float*)d_in[1];
  const float* boff = (const float*)d_in[2];
  const float* Wm = (const float*)d_in[3];
  const float* bias = (const float*)d_in[4];
  float* out = (float*)d_out;

  const int smem_bytes = 3 * 32768 + 1024;
  cudaFuncSetAttribute(gemm_kernel, cudaFuncAttributeMaxDynamicSharedMemorySize,
                       smem_bytes);

  prep_kernel<<<16384 + 2592, 256>>>(x, Wm);
  offsample_kernel<<<1024, 256>>>(x, Woff, boff);
  gemm_kernel<<<1024, 256, smem_bytes>>>(bias, out);
}